// round 7
// baseline (speedup 1.0000x reference)
#include <cuda_runtime.h>
#include <cstdint>
#include <cstddef>

#define B_ 64
#define T_ 320
#define H_ 256
#define D_ 512
#define NR (B_*T_)   // 20480

// ---------------- device scratch (sanctioned: __device__ globals) ----------------
static __device__ float g_cwm [(size_t)NR*D_];
static __device__ float g_cm  [(size_t)NR*D_];
static __device__ float g_att [(size_t)B_*T_*T_];
static __device__ float g_cell[(size_t)NR*D_];
static __device__ float g_gi  [(size_t)NR*1024];
static __device__ float g_gihf[(size_t)NR*768];
static __device__ float g_gihb[(size_t)NR*768];
static __device__ float g_Wpk [(size_t)2*3*64*256*4];   // [dir][gate][k4][h] float4-of-k
static __device__ float g_H   [2][2*B_*H_];             // [buf][dir*B*H + b*H + h]
static __device__ unsigned g_cnt;
static __device__ unsigned g_gen;

// ---------------- fast transcendentals: 2x MUFU, ~1e-7 rel err ----------------
__device__ __forceinline__ float ex2f_(float x){ float y; asm("ex2.approx.ftz.f32 %0, %1;" : "=f"(y) : "f"(x)); return y; }
__device__ __forceinline__ float rcpf_(float x){ float y; asm("rcp.approx.ftz.f32 %0, %1;" : "=f"(y) : "f"(x)); return y; }
#define LOG2E 1.4426950408889634f
__device__ __forceinline__ float tanh_fast(float x){
    float t = ex2f_(x * (2.0f*LOG2E));              // e^{2x}
    return fmaf(-2.0f, rcpf_(t + 1.0f), 1.0f);      // 1 - 2/(e^{2x}+1)
}
__device__ __forceinline__ float sigm_fast(float x){
    return rcpf_(1.0f + ex2f_(-x * LOG2E));
}

// ---------------- SGEMM: C[M,N] = A[M,K] @ B[N,K]^T + bias[N] ----------------
// A1 != null  : A is virtual [A0 | A1] split at k=512 (both row-stride 512)
// mode == 1   : epilogue  C = P[:,col] * sigmoid(acc+bias)  (P0 cols<512, P1 cols>=512)
__global__ void __launch_bounds__(256) sgemm_tt(
    const float* __restrict__ A0, const float* __restrict__ A1,
    const float* __restrict__ Bm, const float* __restrict__ bias,
    const float* __restrict__ P0, const float* __restrict__ P1,
    float* __restrict__ C, int M, int N, int K, int mode)
{
    __shared__ float As[8][132];
    __shared__ float Bs[8][132];
    const int bm = blockIdx.y * 128;
    const int bn = blockIdx.x * 128;
    const int tid = threadIdx.x;
    const int tx = tid & 15, ty = tid >> 4;
    const int lrow = tid >> 1;
    const int lcol = (tid & 1) << 2;

    float acc[8][8];
#pragma unroll
    for (int i = 0; i < 8; i++)
#pragma unroll
        for (int j = 0; j < 8; j++) acc[i][j] = 0.0f;

    for (int k0 = 0; k0 < K; k0 += 8) {
        float4 av;
        if (A1) {
            int k = k0 + lcol;
            const float* s = (k < 512) ? (A0 + (size_t)(bm + lrow) * 512 + k)
                                       : (A1 + (size_t)(bm + lrow) * 512 + (k - 512));
            av = *(const float4*)s;
        } else {
            av = *(const float4*)(A0 + (size_t)(bm + lrow) * K + k0 + lcol);
        }
        float4 bv = *(const float4*)(Bm + (size_t)(bn + lrow) * K + k0 + lcol);
        As[lcol + 0][lrow] = av.x; As[lcol + 1][lrow] = av.y;
        As[lcol + 2][lrow] = av.z; As[lcol + 3][lrow] = av.w;
        Bs[lcol + 0][lrow] = bv.x; Bs[lcol + 1][lrow] = bv.y;
        Bs[lcol + 2][lrow] = bv.z; Bs[lcol + 3][lrow] = bv.w;
        __syncthreads();
#pragma unroll
        for (int k = 0; k < 8; k++) {
            float a[8], b[8];
            *(float4*)(a)     = *(const float4*)&As[k][ty * 8];
            *(float4*)(a + 4) = *(const float4*)&As[k][ty * 8 + 4];
            *(float4*)(b)     = *(const float4*)&Bs[k][tx * 8];
            *(float4*)(b + 4) = *(const float4*)&Bs[k][tx * 8 + 4];
#pragma unroll
            for (int i = 0; i < 8; i++)
#pragma unroll
                for (int j = 0; j < 8; j++)
                    acc[i][j] = fmaf(a[i], b[j], acc[i][j]);
        }
        __syncthreads();
    }

    float bvv[8];
    {
        float4 lo = *(const float4*)(bias + bn + tx * 8);
        float4 hi = *(const float4*)(bias + bn + tx * 8 + 4);
        bvv[0]=lo.x; bvv[1]=lo.y; bvv[2]=lo.z; bvv[3]=lo.w;
        bvv[4]=hi.x; bvv[5]=hi.y; bvv[6]=hi.z; bvv[7]=hi.w;
    }
    const float* P = nullptr; int cb = 0;
    if (mode == 1) { P = (bn < 512) ? P0 : P1; cb = (bn < 512) ? bn : bn - 512; }

#pragma unroll
    for (int i = 0; i < 8; i++) {
        int row = bm + ty * 8 + i;
        float o[8];
#pragma unroll
        for (int j = 0; j < 8; j++) o[j] = acc[i][j] + bvv[j];
        if (mode == 1) {
            float4 p0 = *(const float4*)(P + (size_t)row * 512 + cb + tx * 8);
            float4 p1 = *(const float4*)(P + (size_t)row * 512 + cb + tx * 8 + 4);
            o[0]=p0.x*sigm_fast(o[0]); o[1]=p0.y*sigm_fast(o[1]);
            o[2]=p0.z*sigm_fast(o[2]); o[3]=p0.w*sigm_fast(o[3]);
            o[4]=p1.x*sigm_fast(o[4]); o[5]=p1.y*sigm_fast(o[5]);
            o[6]=p1.z*sigm_fast(o[6]); o[7]=p1.w*sigm_fast(o[7]);
        }
        *(float4*)(C + (size_t)row * N + bn + tx * 8)     = make_float4(o[0],o[1],o[2],o[3]);
        *(float4*)(C + (size_t)row * N + bn + tx * 8 + 4) = make_float4(o[4],o[5],o[6],o[7]);
    }
}

// ------- scores[b,t,t'] = sum_d v[b,t,d] * tanh(cwm[b,t,d] + cm[b,t',d]) -------
__global__ void __launch_bounds__(256) scores_k(const float* __restrict__ v)
{
    __shared__ float sC[16][68];   // cwm[d][t]
    __shared__ float sV[16][68];   // v  [d][t]
    __shared__ float sM[16][68];   // cm [d][t']
    const int b  = blockIdx.z;
    const int t0 = blockIdx.y * 64;
    const int p0 = blockIdx.x * 64;
    const int tid = threadIdx.x;
    const int tx = tid & 15, ty = tid >> 4;
    const int row = tid >> 2;
    const int c4  = (tid & 3) << 2;

    float acc[4][4];
#pragma unroll
    for (int i = 0; i < 4; i++)
#pragma unroll
        for (int j = 0; j < 4; j++) acc[i][j] = 0.0f;

    const size_t baseT = ((size_t)b * T_ + t0 + row) * D_;
    const size_t baseP = ((size_t)b * T_ + p0 + row) * D_;

    for (int d0 = 0; d0 < D_; d0 += 16) {
        float4 cc = *(const float4*)(g_cwm + baseT + d0 + c4);
        float4 vv = *(const float4*)(v     + baseT + d0 + c4);
        float4 mm = *(const float4*)(g_cm  + baseP + d0 + c4);
        sC[c4+0][row]=cc.x; sC[c4+1][row]=cc.y; sC[c4+2][row]=cc.z; sC[c4+3][row]=cc.w;
        sV[c4+0][row]=vv.x; sV[c4+1][row]=vv.y; sV[c4+2][row]=vv.z; sV[c4+3][row]=vv.w;
        sM[c4+0][row]=mm.x; sM[c4+1][row]=mm.y; sM[c4+2][row]=mm.z; sM[c4+3][row]=mm.w;
        __syncthreads();
#pragma unroll
        for (int k = 0; k < 16; k++) {
            float a[4], av[4], bb[4];
            *(float4*)a  = *(const float4*)&sC[k][ty * 4];
            *(float4*)av = *(const float4*)&sV[k][ty * 4];
            *(float4*)bb = *(const float4*)&sM[k][tx * 4];
#pragma unroll
            for (int i = 0; i < 4; i++)
#pragma unroll
                for (int j = 0; j < 4; j++)
                    acc[i][j] = fmaf(av[i], tanh_fast(a[i] + bb[j]), acc[i][j]);
        }
        __syncthreads();
    }
#pragma unroll
    for (int i = 0; i < 4; i++) {
        size_t orow = ((size_t)b * T_ + t0 + ty * 4 + i) * T_ + p0 + tx * 4;
        *(float4*)(g_att + orow) = make_float4(acc[i][0], acc[i][1], acc[i][2], acc[i][3]);
    }
}

// ---------------- softmax over rows of length 320 (warp per row) ----------------
__global__ void __launch_bounds__(256) softmax_k()
{
    int w   = threadIdx.x >> 5;
    int lane = threadIdx.x & 31;
    int row = blockIdx.x * 8 + w;          // 2560 blocks * 8 = 20480 rows
    float* p = g_att + (size_t)row * T_;
    float x[10];
#pragma unroll
    for (int i = 0; i < 10; i++) x[i] = p[i * 32 + lane];
    float m = x[0];
#pragma unroll
    for (int i = 1; i < 10; i++) m = fmaxf(m, x[i]);
#pragma unroll
    for (int o = 16; o > 0; o >>= 1) m = fmaxf(m, __shfl_xor_sync(0xffffffffu, m, o));
    float s = 0.0f;
#pragma unroll
    for (int i = 0; i < 10; i++) { x[i] = ex2f_((x[i] - m) * LOG2E); s += x[i]; }
#pragma unroll
    for (int o = 16; o > 0; o >>= 1) s += __shfl_xor_sync(0xffffffffu, s, o);
    float inv = rcpf_(s);
#pragma unroll
    for (int i = 0; i < 10; i++) p[i * 32 + lane] = x[i] * inv;
}

// ---------------- cell[b,t,d] = sum_t' attn[b,t,t'] * v[b,t',d] ----------------
__global__ void __launch_bounds__(256) cell_k(const float* __restrict__ v)
{
    __shared__ float sA[16][68];   // attn[k][t]
    __shared__ float sB[16][68];   // v   [k][d]
    const int b  = blockIdx.z;
    const int t0 = blockIdx.y * 64;
    const int d0 = blockIdx.x * 64;
    const int tid = threadIdx.x;
    const int tx = tid & 15, ty = tid >> 4;
    const int arow = tid >> 2, ac4 = (tid & 3) << 2;
    const int brow = tid >> 4, bc4 = (tid & 15) << 2;

    float acc[4][4];
#pragma unroll
    for (int i = 0; i < 4; i++)
#pragma unroll
        for (int j = 0; j < 4; j++) acc[i][j] = 0.0f;

    for (int k0 = 0; k0 < T_; k0 += 16) {
        float4 a4 = *(const float4*)(g_att + ((size_t)b * T_ + t0 + arow) * T_ + k0 + ac4);
        sA[ac4+0][arow]=a4.x; sA[ac4+1][arow]=a4.y; sA[ac4+2][arow]=a4.z; sA[ac4+3][arow]=a4.w;
        float4 b4 = *(const float4*)(v + ((size_t)b * T_ + k0 + brow) * D_ + d0 + bc4);
        *(float4*)&sB[brow][bc4] = b4;
        __syncthreads();
#pragma unroll
        for (int k = 0; k < 16; k++) {
            float a[4], bb[4];
            *(float4*)a  = *(const float4*)&sA[k][ty * 4];
            *(float4*)bb = *(const float4*)&sB[k][tx * 4];
#pragma unroll
            for (int i = 0; i < 4; i++)
#pragma unroll
                for (int j = 0; j < 4; j++)
                    acc[i][j] = fmaf(a[i], bb[j], acc[i][j]);
        }
        __syncthreads();
    }
#pragma unroll
    for (int i = 0; i < 4; i++) {
        size_t orow = ((size_t)b * T_ + t0 + ty * 4 + i) * D_ + d0 + tx * 4;
        *(float4*)(g_cell + orow) = make_float4(acc[i][0], acc[i][1], acc[i][2], acc[i][3]);
    }
}

// ------- pack Whh -> [dir][gate][k4][h] as float4-of-k (coalesced over h) -------
__global__ void __launch_bounds__(256) pack_whh(const float* __restrict__ Wf,
                                               const float* __restrict__ Wb)
{
    int i = blockIdx.x * 256 + threadIdx.x;      // 98304 float4 slots
    int dir = i / 49152;
    int r   = i % 49152;
    int g   = r / 16384;
    int k4  = (r >> 8) & 63;
    int h   = r & 255;
    const float* W = dir ? Wb : Wf;
    float4 val = *(const float4*)(W + (size_t)(g * 256 + h) * 256 + k4 * 4);
    ((float4*)g_Wpk)[i] = val;
}

// ---------------- persistent GRU recurrence, 128 CTAs, grid barrier ----------------
__device__ __forceinline__ void gridbar()
{
    __syncthreads();
    if (threadIdx.x == 0) {
        __threadfence();
        unsigned g = *(volatile unsigned*)&g_gen;
        unsigned a = atomicAdd(&g_cnt, 1u);
        if (a == 127u) {
            g_cnt = 0u;
            __threadfence();
            atomicAdd(&g_gen, 1u);
        } else {
            while (*(volatile unsigned*)&g_gen == g) { }
        }
        __threadfence();
    }
    __syncthreads();
}

__global__ void __launch_bounds__(256) recur_k(
    const float* __restrict__ gihf, const float* __restrict__ gihb,
    const float* __restrict__ bhhf, const float* __restrict__ bhhb,
    float* __restrict__ out)
{
    const int bid = blockIdx.x;            // 128 = 2 dir * 8 hb * 8 bb
    const int dir = bid >> 6;
    const int hb  = (bid >> 3) & 7;
    const int bb  = bid & 7;
    const int tid = threadIdx.x;
    const int hl  = tid & 31;
    const int bl  = tid >> 5;
    const int h   = hb * 32 + hl;
    const int b   = bb * 8 + bl;

    const float* gih = dir ? gihb : gihf;
    const float* bhh = dir ? bhhb : bhhf;
    const float bhr = bhh[h], bhz = bhh[256 + h], bhn = bhh[512 + h];

    __shared__ float sh[8 * 256];

    // zero initial hidden state (buf 0); each (dir,b,h) written exactly once
    g_H[0][dir * 16384 + b * 256 + h] = 0.0f;
    gridbar();

    int buf = 0;
    const float4* Wbase = (const float4*)g_Wpk + (size_t)dir * 3 * 64 * 256;
    const float4* wr = Wbase + 0 * 16384 + h;
    const float4* wz = Wbase + 1 * 16384 + h;
    const float4* wn = Wbase + 2 * 16384 + h;

    for (int t = 0; t < T_; t++) {
        {   // stage h_prev[dir][bb*8 .. +8][:] into shared (bypass L1: cross-SM producer)
            const float4* src = (const float4*)(g_H[buf] + dir * 16384 + bb * 8 * 256);
            float4* dst = (float4*)sh;
            dst[tid]       = __ldcg(src + tid);
            dst[tid + 256] = __ldcg(src + tid + 256);
        }
        __syncthreads();

        float ar = 0.0f, az = 0.0f, an = 0.0f;
        const float4* hv = (const float4*)(sh + bl * 256);
#pragma unroll 4
        for (int k4 = 0; k4 < 64; k4++) {
            float4 h4 = hv[k4];
            float4 a = wr[(size_t)k4 * 256];
            float4 c = wz[(size_t)k4 * 256];
            float4 d = wn[(size_t)k4 * 256];
            ar = fmaf(a.x,h4.x, fmaf(a.y,h4.y, fmaf(a.z,h4.z, fmaf(a.w,h4.w, ar))));
            az = fmaf(c.x,h4.x, fmaf(c.y,h4.y, fmaf(c.z,h4.z, fmaf(c.w,h4.w, az))));
            an = fmaf(d.x,h4.x, fmaf(d.y,h4.y, fmaf(d.z,h4.z, fmaf(d.w,h4.w, an))));
        }

        size_t gb = ((size_t)b * T_ + t) * 768;
        float ir = gih[gb + h], iz = gih[gb + 256 + h], in_ = gih[gb + 512 + h];
        float r = sigm_fast(ir + ar + bhr);
        float z = sigm_fast(iz + az + bhz);
        float n = tanh_fast(in_ + r * (an + bhn));
        float hp = sh[bl * 256 + h];
        float hn = (1.0f - z) * n + z * hp;

        g_H[buf ^ 1][dir * 16384 + b * 256 + h] = hn;
        out[((size_t)t * B_ + b) * 512 + dir * 256 + h] = hn;
        buf ^= 1;
        gridbar();
    }
}

// ---------------- launcher ----------------
extern "C" void kernel_launch(void* const* d_in, const int* in_sizes, int n_in,
                              void* d_out, int out_size)
{
    const float* v     = (const float*)d_in[0];
    const float* W1    = (const float*)d_in[1];
    const float* b1    = (const float*)d_in[2];
    const float* W2    = (const float*)d_in[3];
    const float* b2    = (const float*)d_in[4];
    const float* Wg    = (const float*)d_in[5];
    const float* bg    = (const float*)d_in[6];
    const float* Wih_f = (const float*)d_in[7];
    const float* Whh_f = (const float*)d_in[8];
    const float* bih_f = (const float*)d_in[9];
    const float* bhh_f = (const float*)d_in[10];
    const float* Wih_b = (const float*)d_in[11];
    const float* Whh_b = (const float*)d_in[12];
    const float* bih_b = (const float*)d_in[13];
    const float* bhh_b = (const float*)d_in[14];
    float* out = (float*)d_out;

    float *p_cwm, *p_cm, *p_cell, *p_gi, *p_gihf, *p_gihb;
    cudaGetSymbolAddress((void**)&p_cwm,  g_cwm);
    cudaGetSymbolAddress((void**)&p_cm,   g_cm);
    cudaGetSymbolAddress((void**)&p_cell, g_cell);
    cudaGetSymbolAddress((void**)&p_gi,   g_gi);
    cudaGetSymbolAddress((void**)&p_gihf, g_gihf);
    cudaGetSymbolAddress((void**)&p_gihb, g_gihb);

    // Whh transpose/pack (cheap, every call -> deterministic)
    pack_whh<<<384, 256>>>(Whh_f, Whh_b);

    // cwm = v @ W1^T + b1 ; cm = v @ W2^T + b2
    sgemm_tt<<<dim3(4, 160), 256>>>(v, nullptr, W1, b1, nullptr, nullptr,
                                    p_cwm, NR, 512, 512, 0);
    sgemm_tt<<<dim3(4, 160), 256>>>(v, nullptr, W2, b2, nullptr, nullptr,
                                    p_cm, NR, 512, 512, 0);

    // scores -> softmax -> cell
    scores_k<<<dim3(5, 5, B_), 256>>>(v);
    softmax_k<<<2560, 256>>>();
    cell_k<<<dim3(8, 5, B_), 256>>>(v);

    // gi = pg * sigmoid(pg @ Wg^T + bg), pg = [v | cell]
    sgemm_tt<<<dim3(8, 160), 256>>>(v, p_cell, Wg, bg, v, p_cell,
                                    p_gi, NR, 1024, 1024, 1);

    // gih_{f,b} = gi @ Wih^T + bih
    sgemm_tt<<<dim3(6, 160), 256>>>(p_gi, nullptr, Wih_f, bih_f, nullptr, nullptr,
                                    p_gihf, NR, 768, 1024, 0);
    sgemm_tt<<<dim3(6, 160), 256>>>(p_gi, nullptr, Wih_b, bih_b, nullptr, nullptr,
                                    p_gihb, NR, 768, 1024, 0);

    // sequential GRU recurrence, writes d_out directly
    recur_k<<<128, 256>>>(p_gihf, p_gihb, bhh_f, bhh_b, out);
}

// round 10
// speedup vs baseline: 1.2387x; 1.2387x over previous
#include <cuda_runtime.h>
#include <cuda_bf16.h>
#include <cstdint>
#include <cstddef>

#define B_ 64
#define T_ 320
#define H_ 256
#define D_ 512
#define NR (B_*T_)   // 20480

// ---------------- device scratch ----------------
static __device__ float g_cwm [(size_t)NR*D_];
static __device__ float g_cm  [(size_t)NR*D_];
static __device__ float g_att [(size_t)B_*T_*T_];
static __device__ float g_cell[(size_t)NR*D_];
static __device__ float g_gi  [(size_t)NR*1024];
static __device__ float g_gihf[(size_t)NR*768];
static __device__ float g_gihb[(size_t)NR*768];
static __device__ float g_Wpk [(size_t)2*3*64*256*4];
static __device__ float g_H   [2][2*B_*H_];
static __device__ unsigned g_cnt;
static __device__ unsigned g_gen;

// ---------------- fast transcendentals ----------------
__device__ __forceinline__ float ex2f_(float x){ float y; asm("ex2.approx.ftz.f32 %0, %1;" : "=f"(y) : "f"(x)); return y; }
__device__ __forceinline__ float rcpf_(float x){ float y; asm("rcp.approx.ftz.f32 %0, %1;" : "=f"(y) : "f"(x)); return y; }
#define LOG2E 1.4426950408889634f
__device__ __forceinline__ float tanh_fast(float x){
    float t = ex2f_(x * (2.0f*LOG2E));
    return fmaf(-2.0f, rcpf_(t + 1.0f), 1.0f);
}
__device__ __forceinline__ float sigm_fast(float x){
    return rcpf_(1.0f + ex2f_(-x * LOG2E));
}

__device__ __forceinline__ uint32_t smem_u32(const void* p){
    uint32_t a;
    asm("{ .reg .u64 t; cvta.to.shared.u64 t, %1; cvt.u32.u64 %0, t; }" : "=r"(a) : "l"(p));
    return a;
}

// ---------------- HMMA helpers (mma.sync, sm_80-class: no arch-suffix gating) -------------
__device__ __forceinline__ void ldm4(uint32_t a, uint32_t* r){
    asm volatile("ldmatrix.sync.aligned.m8n8.x4.shared.b16 {%0,%1,%2,%3}, [%4];"
        : "=r"(r[0]), "=r"(r[1]), "=r"(r[2]), "=r"(r[3]) : "r"(a));
}
__device__ __forceinline__ void mma_bf16(float* c, const uint32_t* a, uint32_t b0, uint32_t b1){
    asm volatile("mma.sync.aligned.m16n8k16.row.col.f32.bf16.bf16.f32 "
        "{%0,%1,%2,%3}, {%4,%5,%6,%7}, {%8,%9}, {%0,%1,%2,%3};"
        : "+f"(c[0]), "+f"(c[1]), "+f"(c[2]), "+f"(c[3])
        : "r"(a[0]), "r"(a[1]), "r"(a[2]), "r"(a[3]), "r"(b0), "r"(b1));
}

// smem tile layout: bf16 [128 rows][32 cols] pitch 40 elems (80B rows -> conflict-free ldmatrix)
#define PK 40
#define TILE_B (128*PK*2)        // 10240 bytes per bf16 tile
#define STAGE_B (4*TILE_B)       // Ah, Al, Bh, Bl = 40960
#define GSM_TOTAL (2*STAGE_B)    // double buffer = 81920

__device__ __forceinline__ void st_hilo(uint32_t th, uint32_t tl, int row, int c4, float4 f){
    __nv_bfloat162 h01 = __floats2bfloat162_rn(f.x, f.y);
    __nv_bfloat162 h23 = __floats2bfloat162_rn(f.z, f.w);
    float2 hf01 = __bfloat1622float2(h01);
    float2 hf23 = __bfloat1622float2(h23);
    __nv_bfloat162 l01 = __floats2bfloat162_rn(f.x - hf01.x, f.y - hf01.y);
    __nv_bfloat162 l23 = __floats2bfloat162_rn(f.z - hf23.x, f.w - hf23.y);
    uint32_t off = (uint32_t)(row * PK + c4) * 2u;
    uint32_t h0 = *reinterpret_cast<uint32_t*>(&h01);
    uint32_t h1 = *reinterpret_cast<uint32_t*>(&h23);
    uint32_t l0 = *reinterpret_cast<uint32_t*>(&l01);
    uint32_t l1 = *reinterpret_cast<uint32_t*>(&l23);
    asm volatile("st.shared.v2.b32 [%0], {%1, %2};" :: "r"(th + off), "r"(h0), "r"(h1) : "memory");
    asm volatile("st.shared.v2.b32 [%0], {%1, %2};" :: "r"(tl + off), "r"(l0), "r"(l1) : "memory");
}

// ------------- tensor-core GEMM (HMMA): C[.,N] = A @ B^T + bias, bf16 hi/lo split -------------
// grid = (N/128, M/128). A1 != null: A is virtual [A0|A1] split at k=512 (row stride 512 each)
// mode 1: C = P[:,col] * sigmoid(acc+bias),  P0 for cols<512, P1 for cols>=512
__global__ void __launch_bounds__(256) gemm_tc(
    const float* __restrict__ A0, const float* __restrict__ A1,
    const float* __restrict__ Bm, const float* __restrict__ bias,
    const float* __restrict__ P0, const float* __restrict__ P1,
    float* __restrict__ C, int N, int K, int mode)
{
    extern __shared__ char sm[];
    const uint32_t smb = smem_u32(sm);
    const int tid  = threadIdx.x;
    const int bm   = blockIdx.y * 128;
    const int bn   = blockIdx.x * 128;
    const int lane = tid & 31;
    const int wid  = tid >> 5;
    const int wm   = wid & 1;      // 2 warps in M  -> warp M tile 64
    const int wn   = wid >> 1;     // 4 warps in N  -> warp N tile 32

    const int nst = K >> 5;        // BK = 32

    float acc[4][4][4];
#pragma unroll
    for (int i = 0; i < 4; i++)
#pragma unroll
        for (int j = 0; j < 4; j++)
#pragma unroll
            for (int q = 0; q < 4; q++) acc[i][j][q] = 0.0f;

    // ldmatrix per-lane offsets: lanes 0-15 -> rows r..r+15 (k lo half), 16-31 -> (k hi half)
    const int arow = lane & 15;
    const int kcol = (lane >> 4) << 3;

    float4 ra[4], rb[4];

    // ---- gmem stage load into regs
    auto load_regs = [&](int s){
        const int kbase = s << 5;
#pragma unroll
        for (int it = 0; it < 4; it++) {
            int li  = it * 256 + tid;
            int row = li >> 3;
            int c4  = (li & 7) << 2;
            int kg  = kbase + c4;
            const float* sa;
            if (A1) sa = (kg < 512) ? (A0 + (size_t)(bm + row) * 512 + kg)
                                    : (A1 + (size_t)(bm + row) * 512 + (kg - 512));
            else    sa = A0 + (size_t)(bm + row) * K + kg;
            ra[it] = *(const float4*)sa;
            rb[it] = *(const float4*)(Bm + (size_t)(bn + row) * K + kg);
        }
    };
    auto store_regs = [&](int s){
        uint32_t sb = smb + (uint32_t)(s & 1) * STAGE_B;
#pragma unroll
        for (int it = 0; it < 4; it++) {
            int li  = it * 256 + tid;
            int row = li >> 3;
            int c4  = (li & 7) << 2;
            st_hilo(sb,              sb + TILE_B,     row, c4, ra[it]);
            st_hilo(sb + 2*TILE_B,   sb + 3*TILE_B,   row, c4, rb[it]);
        }
    };

    load_regs(0);
    store_regs(0);
    __syncthreads();

    for (int s = 0; s < nst; s++) {
        if (s + 1 < nst) load_regs(s + 1);

        const uint32_t sb = smb + (uint32_t)(s & 1) * STAGE_B;
#pragma unroll
        for (int ks = 0; ks < 2; ks++) {
            const int k0 = ks << 4;
            uint32_t bh[2][4], bl[2][4];
            {
                uint32_t bb = sb + 2*TILE_B + (uint32_t)((wn * 32 + arow) * PK + k0 + kcol) * 2u;
                ldm4(bb,              bh[0]);
                ldm4(bb + 16*PK*2,    bh[1]);
                ldm4(bb + TILE_B,           bl[0]);
                ldm4(bb + TILE_B + 16*PK*2, bl[1]);
            }
            const uint32_t ab = sb + (uint32_t)((wm * 64 + arow) * PK + k0 + kcol) * 2u;
#pragma unroll
            for (int i = 0; i < 4; i++) {
                uint32_t ah[4], al[4];
                ldm4(ab + (uint32_t)(i * 16 * PK * 2),          ah);
                ldm4(ab + (uint32_t)(i * 16 * PK * 2) + TILE_B, al);
#pragma unroll
                for (int j = 0; j < 4; j++) {
                    uint32_t b0h = bh[j >> 1][j & 1], b1h = bh[j >> 1][(j & 1) + 2];
                    mma_bf16(acc[i][j], ah, b0h, b1h);
                    mma_bf16(acc[i][j], al, b0h, b1h);
                    uint32_t b0l = bl[j >> 1][j & 1], b1l = bl[j >> 1][(j & 1) + 2];
                    mma_bf16(acc[i][j], ah, b0l, b1l);
                }
            }
        }

        if (s + 1 < nst) store_regs(s + 1);
        __syncthreads();
    }

    // ---- epilogue: fragment layout d0,d1 -> (row, col..col+1), d2,d3 -> (row+8, col..col+1)
    const int r0b = bm + wm * 64 + (lane >> 2);
    const int c0b = bn + wn * 32 + ((lane & 3) << 1);
#pragma unroll
    for (int i = 0; i < 4; i++) {
#pragma unroll
        for (int j = 0; j < 4; j++) {
            int row = r0b + i * 16;
            int col = c0b + j * 8;
            float bz0 = bias[col], bz1 = bias[col + 1];
            float o0 = acc[i][j][0] + bz0;
            float o1 = acc[i][j][1] + bz1;
            float o2 = acc[i][j][2] + bz0;
            float o3 = acc[i][j][3] + bz1;
            if (mode == 1) {
                const float* P = (col < 512) ? P0 : P1;
                int cc = (col < 512) ? col : col - 512;
                float2 p0 = *(const float2*)(P + (size_t)row * 512 + cc);
                float2 p1 = *(const float2*)(P + (size_t)(row + 8) * 512 + cc);
                o0 = p0.x * sigm_fast(o0); o1 = p0.y * sigm_fast(o1);
                o2 = p1.x * sigm_fast(o2); o3 = p1.y * sigm_fast(o3);
            }
            *(float2*)(C + (size_t)row * N + col)       = make_float2(o0, o1);
            *(float2*)(C + (size_t)(row + 8) * N + col) = make_float2(o2, o3);
        }
    }
}

// ------- scores[b,t,t'] = sum_d v[b,t,d] * tanh(cwm[b,t,d] + cm[b,t',d]) -------
__global__ void __launch_bounds__(256) scores_k(const float* __restrict__ v)
{
    __shared__ float sC[16][68];
    __shared__ float sV[16][68];
    __shared__ float sM[16][68];
    const int b  = blockIdx.z;
    const int t0 = blockIdx.y * 64;
    const int p0 = blockIdx.x * 64;
    const int tid = threadIdx.x;
    const int tx = tid & 15, ty = tid >> 4;
    const int row = tid >> 2;
    const int c4  = (tid & 3) << 2;

    float acc[4][4];
#pragma unroll
    for (int i = 0; i < 4; i++)
#pragma unroll
        for (int j = 0; j < 4; j++) acc[i][j] = 0.0f;

    const size_t baseT = ((size_t)b * T_ + t0 + row) * D_;
    const size_t baseP = ((size_t)b * T_ + p0 + row) * D_;

    for (int d0 = 0; d0 < D_; d0 += 16) {
        float4 cc = *(const float4*)(g_cwm + baseT + d0 + c4);
        float4 vv = *(const float4*)(v     + baseT + d0 + c4);
        float4 mm = *(const float4*)(g_cm  + baseP + d0 + c4);
        sC[c4+0][row]=cc.x; sC[c4+1][row]=cc.y; sC[c4+2][row]=cc.z; sC[c4+3][row]=cc.w;
        sV[c4+0][row]=vv.x; sV[c4+1][row]=vv.y; sV[c4+2][row]=vv.z; sV[c4+3][row]=vv.w;
        sM[c4+0][row]=mm.x; sM[c4+1][row]=mm.y; sM[c4+2][row]=mm.z; sM[c4+3][row]=mm.w;
        __syncthreads();
#pragma unroll
        for (int k = 0; k < 16; k++) {
            float a[4], av[4], bb[4];
            *(float4*)a  = *(const float4*)&sC[k][ty * 4];
            *(float4*)av = *(const float4*)&sV[k][ty * 4];
            *(float4*)bb = *(const float4*)&sM[k][tx * 4];
#pragma unroll
            for (int i = 0; i < 4; i++)
#pragma unroll
                for (int j = 0; j < 4; j++)
                    acc[i][j] = fmaf(av[i], tanh_fast(a[i] + bb[j]), acc[i][j]);
        }
        __syncthreads();
    }
#pragma unroll
    for (int i = 0; i < 4; i++) {
        size_t orow = ((size_t)b * T_ + t0 + ty * 4 + i) * T_ + p0 + tx * 4;
        *(float4*)(g_att + orow) = make_float4(acc[i][0], acc[i][1], acc[i][2], acc[i][3]);
    }
}

// ---------------- softmax over rows of length 320 (warp per row) ----------------
__global__ void __launch_bounds__(256) softmax_k()
{
    int w    = threadIdx.x >> 5;
    int lane = threadIdx.x & 31;
    int row  = blockIdx.x * 8 + w;
    float* p = g_att + (size_t)row * T_;
    float x[10];
#pragma unroll
    for (int i = 0; i < 10; i++) x[i] = p[i * 32 + lane];
    float m = x[0];
#pragma unroll
    for (int i = 1; i < 10; i++) m = fmaxf(m, x[i]);
#pragma unroll
    for (int o = 16; o > 0; o >>= 1) m = fmaxf(m, __shfl_xor_sync(0xffffffffu, m, o));
    float s = 0.0f;
#pragma unroll
    for (int i = 0; i < 10; i++) { x[i] = ex2f_((x[i] - m) * LOG2E); s += x[i]; }
#pragma unroll
    for (int o = 16; o > 0; o >>= 1) s += __shfl_xor_sync(0xffffffffu, s, o);
    float inv = rcpf_(s);
#pragma unroll
    for (int i = 0; i < 10; i++) p[i * 32 + lane] = x[i] * inv;
}

// ---------------- cell[b,t,d] = sum_t' attn[b,t,t'] * v[b,t',d] ----------------
__global__ void __launch_bounds__(256) cell_k(const float* __restrict__ v)
{
    __shared__ float sA[16][68];
    __shared__ float sB[16][68];
    const int b  = blockIdx.z;
    const int t0 = blockIdx.y * 64;
    const int d0 = blockIdx.x * 64;
    const int tid = threadIdx.x;
    const int tx = tid & 15, ty = tid >> 4;
    const int arow = tid >> 2, ac4 = (tid & 3) << 2;
    const int brow = tid >> 4, bc4 = (tid & 15) << 2;

    float acc[4][4];
#pragma unroll
    for (int i = 0; i < 4; i++)
#pragma unroll
        for (int j = 0; j < 4; j++) acc[i][j] = 0.0f;

    for (int k0 = 0; k0 < T_; k0 += 16) {
        float4 a4 = *(const float4*)(g_att + ((size_t)b * T_ + t0 + arow) * T_ + k0 + ac4);
        sA[ac4+0][arow]=a4.x; sA[ac4+1][arow]=a4.y; sA[ac4+2][arow]=a4.z; sA[ac4+3][arow]=a4.w;
        float4 b4 = *(const float4*)(v + ((size_t)b * T_ + k0 + brow) * D_ + d0 + bc4);
        *(float4*)&sB[brow][bc4] = b4;
        __syncthreads();
#pragma unroll
        for (int k = 0; k < 16; k++) {
            float a[4], bb[4];
            *(float4*)a  = *(const float4*)&sA[k][ty * 4];
            *(float4*)bb = *(const float4*)&sB[k][tx * 4];
#pragma unroll
            for (int i = 0; i < 4; i++)
#pragma unroll
                for (int j = 0; j < 4; j++)
                    acc[i][j] = fmaf(a[i], bb[j], acc[i][j]);
        }
        __syncthreads();
    }
#pragma unroll
    for (int i = 0; i < 4; i++) {
        size_t orow = ((size_t)b * T_ + t0 + ty * 4 + i) * D_ + d0 + tx * 4;
        *(float4*)(g_cell + orow) = make_float4(acc[i][0], acc[i][1], acc[i][2], acc[i][3]);
    }
}

// ------- pack Whh -> [dir][gate][k4][h] as float4-of-k -------
__global__ void __launch_bounds__(256) pack_whh(const float* __restrict__ Wf,
                                               const float* __restrict__ Wb)
{
    int i = blockIdx.x * 256 + threadIdx.x;
    int dir = i / 49152;
    int r   = i % 49152;
    int g   = r / 16384;
    int k4  = (r >> 8) & 63;
    int h   = r & 255;
    const float* W = dir ? Wb : Wf;
    float4 val = *(const float4*)(W + (size_t)(g * 256 + h) * 256 + k4 * 4);
    ((float4*)g_Wpk)[i] = val;
}

// ---------------- persistent GRU recurrence ----------------
__device__ __forceinline__ void gridbar()
{
    __syncthreads();
    if (threadIdx.x == 0) {
        __threadfence();
        unsigned g = *(volatile unsigned*)&g_gen;
        unsigned a = atomicAdd(&g_cnt, 1u);
        if (a == 127u) {
            g_cnt = 0u;
            __threadfence();
            atomicAdd(&g_gen, 1u);
        } else {
            while (*(volatile unsigned*)&g_gen == g) { }
        }
        __threadfence();
    }
    __syncthreads();
}

__global__ void __launch_bounds__(256) recur_k(
    const float* __restrict__ gihf, const float* __restrict__ gihb,
    const float* __restrict__ bhhf, const float* __restrict__ bhhb,
    float* __restrict__ out)
{
    const int bid = blockIdx.x;
    const int dir = bid >> 6;
    const int hb  = (bid >> 3) & 7;
    const int bb  = bid & 7;
    const int tid = threadIdx.x;
    const int hl  = tid & 31;
    const int bl  = tid >> 5;
    const int h   = hb * 32 + hl;
    const int b   = bb * 8 + bl;

    const float* gih = dir ? gihb : gihf;
    const float* bhh = dir ? bhhb : bhhf;
    const float bhr = bhh[h], bhz = bhh[256 + h], bhn = bhh[512 + h];

    __shared__ float sh[8 * 256];

    g_H[0][dir * 16384 + b * 256 + h] = 0.0f;
    gridbar();

    int buf = 0;
    const float4* Wbase = (const float4*)g_Wpk + (size_t)dir * 3 * 64 * 256;
    const float4* wr = Wbase + 0 * 16384 + h;
    const float4* wz = Wbase + 1 * 16384 + h;
    const float4* wn = Wbase + 2 * 16384 + h;

    for (int t = 0; t < T_; t++) {
        {
            const float4* src = (const float4*)(g_H[buf] + dir * 16384 + bb * 8 * 256);
            float4* dst = (float4*)sh;
            dst[tid]       = __ldcg(src + tid);
            dst[tid + 256] = __ldcg(src + tid + 256);
        }
        __syncthreads();

        float ar = 0.0f, az = 0.0f, an = 0.0f;
        const float4* hv = (const float4*)(sh + bl * 256);
#pragma unroll 4
        for (int k4 = 0; k4 < 64; k4++) {
            float4 h4 = hv[k4];
            float4 a = wr[(size_t)k4 * 256];
            float4 c = wz[(size_t)k4 * 256];
            float4 d = wn[(size_t)k4 * 256];
            ar = fmaf(a.x,h4.x, fmaf(a.y,h4.y, fmaf(a.z,h4.z, fmaf(a.w,h4.w, ar))));
            az = fmaf(c.x,h4.x, fmaf(c.y,h4.y, fmaf(c.z,h4.z, fmaf(c.w,h4.w, az))));
            an = fmaf(d.x,h4.x, fmaf(d.y,h4.y, fmaf(d.z,h4.z, fmaf(d.w,h4.w, an))));
        }

        size_t gb = ((size_t)b * T_ + t) * 768;
        float ir = gih[gb + h], iz = gih[gb + 256 + h], in_ = gih[gb + 512 + h];
        float r = sigm_fast(ir + ar + bhr);
        float z = sigm_fast(iz + az + bhz);
        float n = tanh_fast(in_ + r * (an + bhn));
        float hp = sh[bl * 256 + h];
        float hn = (1.0f - z) * n + z * hp;

        g_H[buf ^ 1][dir * 16384 + b * 256 + h] = hn;
        out[((size_t)t * B_ + b) * 512 + dir * 256 + h] = hn;
        buf ^= 1;
        gridbar();
    }
}

// ---------------- launcher ----------------
extern "C" void kernel_launch(void* const* d_in, const int* in_sizes, int n_in,
                              void* d_out, int out_size)
{
    const float* v     = (const float*)d_in[0];
    const float* W1    = (const float*)d_in[1];
    const float* b1    = (const float*)d_in[2];
    const float* W2    = (const float*)d_in[3];
    const float* b2    = (const float*)d_in[4];
    const float* Wg    = (const float*)d_in[5];
    const float* bg    = (const float*)d_in[6];
    const float* Wih_f = (const float*)d_in[7];
    const float* Whh_f = (const float*)d_in[8];
    const float* bih_f = (const float*)d_in[9];
    const float* bhh_f = (const float*)d_in[10];
    const float* Wih_b = (const float*)d_in[11];
    const float* Whh_b = (const float*)d_in[12];
    const float* bih_b = (const float*)d_in[13];
    const float* bhh_b = (const float*)d_in[14];
    float* out = (float*)d_out;

    float *p_cwm, *p_cm, *p_cell, *p_gi, *p_gihf, *p_gihb;
    cudaGetSymbolAddress((void**)&p_cwm,  g_cwm);
    cudaGetSymbolAddress((void**)&p_cm,   g_cm);
    cudaGetSymbolAddress((void**)&p_cell, g_cell);
    cudaGetSymbolAddress((void**)&p_gi,   g_gi);
    cudaGetSymbolAddress((void**)&p_gihf, g_gihf);
    cudaGetSymbolAddress((void**)&p_gihb, g_gihb);

    cudaFuncSetAttribute(gemm_tc, cudaFuncAttributeMaxDynamicSharedMemorySize, GSM_TOTAL);

    pack_whh<<<384, 256>>>(Whh_f, Whh_b);

    // cwm = v @ W1^T + b1 ; cm = v @ W2^T + b2   (HMMA bf16 hi/lo)
    gemm_tc<<<dim3(4, 160), 256, GSM_TOTAL>>>(v, nullptr, W1, b1, nullptr, nullptr,
                                              p_cwm, 512, 512, 0);
    gemm_tc<<<dim3(4, 160), 256, GSM_TOTAL>>>(v, nullptr, W2, b2, nullptr, nullptr,
                                              p_cm, 512, 512, 0);

    scores_k<<<dim3(5, 5, B_), 256>>>(v);
    softmax_k<<<2560, 256>>>();
    cell_k<<<dim3(8, 5, B_), 256>>>(v);

    // gi = pg * sigmoid(pg @ Wg^T + bg), pg = [v | cell]   (HMMA, fused epilogue)
    gemm_tc<<<dim3(8, 160), 256, GSM_TOTAL>>>(v, p_cell, Wg, bg, v, p_cell,
                                              p_gi, 1024, 1024, 1);

    // gih_{f,b} = gi @ Wih^T + bih   (HMMA)
    gemm_tc<<<dim3(6, 160), 256, GSM_TOTAL>>>(p_gi, nullptr, Wih_f, bih_f, nullptr, nullptr,
                                              p_gihf, 768, 1024, 0);
    gemm_tc<<<dim3(6, 160), 256, GSM_TOTAL>>>(p_gi, nullptr, Wih_b, bih_b, nullptr, nullptr,
                                              p_gihb, 768, 1024, 0);

    recur_k<<<128, 256>>>(p_gihf, p_gihb, bhh_f, bhh_b, out);
}

// round 12
// speedup vs baseline: 1.3438x; 1.0848x over previous
#include <cuda_runtime.h>
#include <cuda_bf16.h>
#include <cstdint>
#include <cstddef>

#define B_ 64
#define T_ 320
#define H_ 256
#define D_ 512
#define NR (B_*T_)   // 20480

// ---------------- device scratch ----------------
static __device__ float g_cwm [(size_t)NR*D_];
static __device__ float g_cm  [(size_t)NR*D_];
static __device__ float g_att [(size_t)B_*T_*T_];
static __device__ float g_cell[(size_t)NR*D_];
static __device__ float g_gi  [(size_t)NR*1024];
static __device__ float g_gihf[(size_t)NR*768];
static __device__ float g_gihb[(size_t)NR*768];
static __device__ float g_Wpk [(size_t)2*3*64*256*4];
static __device__ float g_W12 [(size_t)1024*512];
static __device__ float g_H   [2][2*B_*H_];
static __device__ unsigned g_cnt2[16*32];
static __device__ unsigned g_gen2[16*32];

// ---------------- fast transcendentals ----------------
__device__ __forceinline__ float ex2f_(float x){ float y; asm("ex2.approx.ftz.f32 %0, %1;" : "=f"(y) : "f"(x)); return y; }
__device__ __forceinline__ float rcpf_(float x){ float y; asm("rcp.approx.ftz.f32 %0, %1;" : "=f"(y) : "f"(x)); return y; }
#define LOG2E 1.4426950408889634f
__device__ __forceinline__ float tanh_fast(float x){
    float t = ex2f_(x * (2.0f*LOG2E));
    return fmaf(-2.0f, rcpf_(t + 1.0f), 1.0f);
}
__device__ __forceinline__ float sigm_fast(float x){
    return rcpf_(1.0f + ex2f_(-x * LOG2E));
}

__device__ __forceinline__ uint32_t smem_u32(const void* p){
    uint32_t a;
    asm("{ .reg .u64 t; cvta.to.shared.u64 t, %1; cvt.u32.u64 %0, t; }" : "=r"(a) : "l"(p));
    return a;
}

// ---------------- HMMA helpers ----------------
__device__ __forceinline__ void ldm4(uint32_t a, uint32_t* r){
    asm volatile("ldmatrix.sync.aligned.m8n8.x4.shared.b16 {%0,%1,%2,%3}, [%4];"
        : "=r"(r[0]), "=r"(r[1]), "=r"(r[2]), "=r"(r[3]) : "r"(a));
}
__device__ __forceinline__ void ldm4t(uint32_t a, uint32_t* r){
    asm volatile("ldmatrix.sync.aligned.m8n8.x4.trans.shared.b16 {%0,%1,%2,%3}, [%4];"
        : "=r"(r[0]), "=r"(r[1]), "=r"(r[2]), "=r"(r[3]) : "r"(a));
}
__device__ __forceinline__ void mma_bf16(float* c, const uint32_t* a, uint32_t b0, uint32_t b1){
    asm volatile("mma.sync.aligned.m16n8k16.row.col.f32.bf16.bf16.f32 "
        "{%0,%1,%2,%3}, {%4,%5,%6,%7}, {%8,%9}, {%0,%1,%2,%3};"
        : "+f"(c[0]), "+f"(c[1]), "+f"(c[2]), "+f"(c[3])
        : "r"(a[0]), "r"(a[1]), "r"(a[2]), "r"(a[3]), "r"(b0), "r"(b1));
}

// hi/lo bf16 split store: generic pitch (elements)
__device__ __forceinline__ void st_hilo_p(uint32_t th, uint32_t tl, int row, int c4, int pitch, float4 f){
    __nv_bfloat162 h01 = __floats2bfloat162_rn(f.x, f.y);
    __nv_bfloat162 h23 = __floats2bfloat162_rn(f.z, f.w);
    float2 hf01 = __bfloat1622float2(h01);
    float2 hf23 = __bfloat1622float2(h23);
    __nv_bfloat162 l01 = __floats2bfloat162_rn(f.x - hf01.x, f.y - hf01.y);
    __nv_bfloat162 l23 = __floats2bfloat162_rn(f.z - hf23.x, f.w - hf23.y);
    uint32_t off = (uint32_t)(row * pitch + c4) * 2u;
    uint32_t h0 = *reinterpret_cast<uint32_t*>(&h01);
    uint32_t h1 = *reinterpret_cast<uint32_t*>(&h23);
    uint32_t l0 = *reinterpret_cast<uint32_t*>(&l01);
    uint32_t l1 = *reinterpret_cast<uint32_t*>(&l23);
    asm volatile("st.shared.v2.b32 [%0], {%1, %2};" :: "r"(th + off), "r"(h0), "r"(h1) : "memory");
    asm volatile("st.shared.v2.b32 [%0], {%1, %2};" :: "r"(tl + off), "r"(l0), "r"(l1) : "memory");
}

// ===================== gemm_tc: C = A @ B^T + bias (HMMA, bf16 hi/lo) =====================
// grid (N/128, M/128).  A1 != null: A virtual [A0|A1] split at k=512.
// mode 0: C[row*N+col] = acc + bias[col]
// mode 1: C = P[:,col] * sigmoid(acc + bias[col])  (P0 cols<512, P1 cols>=512)
// mode 2: split output: col<512 -> C (+bias), col>=512 -> C2 (+bias2); both row-stride 512
#define PK 40
#define TILE_B (128*PK*2)
#define STAGE_B (4*TILE_B)
#define GSM_TOTAL (2*STAGE_B)
__global__ void __launch_bounds__(256) gemm_tc(
    const float* __restrict__ A0, const float* __restrict__ A1,
    const float* __restrict__ Bm,
    const float* __restrict__ bias, const float* __restrict__ bias2,
    const float* __restrict__ P0, const float* __restrict__ P1,
    float* __restrict__ C, float* __restrict__ C2,
    int N, int K, int mode)
{
    extern __shared__ char sm[];
    const uint32_t smb = smem_u32(sm);
    const int tid  = threadIdx.x;
    const int bm   = blockIdx.y * 128;
    const int bn   = blockIdx.x * 128;
    const int lane = tid & 31;
    const int wid  = tid >> 5;
    const int wm   = wid & 1;
    const int wn   = wid >> 1;
    const int nst  = K >> 5;

    float acc[4][4][4];
#pragma unroll
    for (int i = 0; i < 4; i++)
#pragma unroll
        for (int j = 0; j < 4; j++)
#pragma unroll
            for (int q = 0; q < 4; q++) acc[i][j][q] = 0.0f;

    const int arow = lane & 15;
    const int kcol = (lane >> 4) << 3;

    float4 ra[4], rb[4];
    auto load_regs = [&](int s){
        const int kbase = s << 5;
#pragma unroll
        for (int it = 0; it < 4; it++) {
            int li  = it * 256 + tid;
            int row = li >> 3;
            int c4  = (li & 7) << 2;
            int kg  = kbase + c4;
            const float* sa;
            if (A1) sa = (kg < 512) ? (A0 + (size_t)(bm + row) * 512 + kg)
                                    : (A1 + (size_t)(bm + row) * 512 + (kg - 512));
            else    sa = A0 + (size_t)(bm + row) * K + kg;
            ra[it] = *(const float4*)sa;
            rb[it] = *(const float4*)(Bm + (size_t)(bn + row) * K + kg);
        }
    };
    auto store_regs = [&](int s){
        uint32_t sb = smb + (uint32_t)(s & 1) * STAGE_B;
#pragma unroll
        for (int it = 0; it < 4; it++) {
            int li  = it * 256 + tid;
            int row = li >> 3;
            int c4  = (li & 7) << 2;
            st_hilo_p(sb,            sb + TILE_B,   row, c4, PK, ra[it]);
            st_hilo_p(sb + 2*TILE_B, sb + 3*TILE_B, row, c4, PK, rb[it]);
        }
    };

    load_regs(0);
    store_regs(0);
    __syncthreads();

    for (int s = 0; s < nst; s++) {
        if (s + 1 < nst) load_regs(s + 1);
        const uint32_t sb = smb + (uint32_t)(s & 1) * STAGE_B;
#pragma unroll
        for (int ks = 0; ks < 2; ks++) {
            const int k0 = ks << 4;
            uint32_t bh[2][4], bl[2][4];
            {
                uint32_t bb = sb + 2*TILE_B + (uint32_t)((wn * 32 + arow) * PK + k0 + kcol) * 2u;
                ldm4(bb,              bh[0]);
                ldm4(bb + 16*PK*2,    bh[1]);
                ldm4(bb + TILE_B,           bl[0]);
                ldm4(bb + TILE_B + 16*PK*2, bl[1]);
            }
            const uint32_t ab = sb + (uint32_t)((wm * 64 + arow) * PK + k0 + kcol) * 2u;
#pragma unroll
            for (int i = 0; i < 4; i++) {
                uint32_t ah[4], al[4];
                ldm4(ab + (uint32_t)(i * 16 * PK * 2),          ah);
                ldm4(ab + (uint32_t)(i * 16 * PK * 2) + TILE_B, al);
#pragma unroll
                for (int j = 0; j < 4; j++) {
                    uint32_t b0h = bh[j >> 1][j & 1], b1h = bh[j >> 1][(j & 1) + 2];
                    mma_bf16(acc[i][j], ah, b0h, b1h);
                    mma_bf16(acc[i][j], al, b0h, b1h);
                    uint32_t b0l = bl[j >> 1][j & 1], b1l = bl[j >> 1][(j & 1) + 2];
                    mma_bf16(acc[i][j], ah, b0l, b1l);
                }
            }
        }
        if (s + 1 < nst) store_regs(s + 1);
        __syncthreads();
    }

    const int r0b = bm + wm * 64 + (lane >> 2);
    const int c0b = bn + wn * 32 + ((lane & 3) << 1);
#pragma unroll
    for (int i = 0; i < 4; i++) {
#pragma unroll
        for (int j = 0; j < 4; j++) {
            int row = r0b + i * 16;
            int col = c0b + j * 8;
            float* Co = C;
            const float* bp = bias;
            int colo = col, stride = N;
            if (mode == 2) {
                stride = 512;
                if (col >= 512) { Co = C2; bp = bias2; colo = col - 512; }
            }
            float bz0 = bp[colo], bz1 = bp[colo + 1];
            float o0 = acc[i][j][0] + bz0;
            float o1 = acc[i][j][1] + bz1;
            float o2 = acc[i][j][2] + bz0;
            float o3 = acc[i][j][3] + bz1;
            if (mode == 1) {
                const float* P = (col < 512) ? P0 : P1;
                int cc = (col < 512) ? col : col - 512;
                float2 p0 = *(const float2*)(P + (size_t)row * 512 + cc);
                float2 p1 = *(const float2*)(P + (size_t)(row + 8) * 512 + cc);
                o0 = p0.x * sigm_fast(o0); o1 = p0.y * sigm_fast(o1);
                o2 = p1.x * sigm_fast(o2); o3 = p1.y * sigm_fast(o3);
            }
            *(float2*)(Co + (size_t)row * stride + colo)       = make_float2(o0, o1);
            *(float2*)(Co + (size_t)(row + 8) * stride + colo) = make_float2(o2, o3);
        }
    }
}

// ===================== cell_tc: cell[b,t,d] = attn[b,t,:] @ v[b,:,d] (HMMA) =====================
// A = attn (row-major, k contig). B = v tile [k=t'][n=d] natural layout, loaded via ldmatrix.trans.
// grid (512/128, 320/64, 64)
#define PN 136
#define CA_TILE (64*PK*2)                 // 5120
#define CB_TILE (32*PN*2)                 // 8704
#define CSTAGE (2*CA_TILE + 2*CB_TILE)    // 27648
#define CSM_TOTAL (2*CSTAGE)              // 55296
__global__ void __launch_bounds__(256) cell_tc(const float* __restrict__ v)
{
    extern __shared__ char sm[];
    const uint32_t smb = smem_u32(sm);
    const int tid  = threadIdx.x;
    const int b    = blockIdx.z;
    const int t0   = blockIdx.y * 64;
    const int d0   = blockIdx.x * 128;
    const int lane = tid & 31;
    const int wid  = tid >> 5;
    const int wm   = wid & 1;     // 2 warps M (32 rows each)
    const int wn   = wid >> 1;    // 4 warps N (32 cols each)

    const float* attp = g_att + (size_t)b * T_ * T_;
    const float* vp   = v     + (size_t)b * T_ * D_;

    float acc[2][4][4];
#pragma unroll
    for (int i = 0; i < 2; i++)
#pragma unroll
        for (int j = 0; j < 4; j++)
#pragma unroll
            for (int q = 0; q < 4; q++) acc[i][j][q] = 0.0f;

    float4 ra[2], rb[4];
    auto load_regs = [&](int s){
        const int k0 = s << 5;
#pragma unroll
        for (int it = 0; it < 2; it++) {
            int li  = it * 256 + tid;
            int row = li >> 3;
            int c4  = (li & 7) << 2;
            ra[it] = *(const float4*)(attp + (size_t)(t0 + row) * T_ + k0 + c4);
        }
#pragma unroll
        for (int it = 0; it < 4; it++) {
            int li  = it * 256 + tid;
            int row = li >> 5;
            int c4  = (li & 31) << 2;
            rb[it] = *(const float4*)(vp + (size_t)(k0 + row) * D_ + d0 + c4);
        }
    };
    auto store_regs = [&](int s){
        uint32_t sb = smb + (uint32_t)(s & 1) * CSTAGE;
#pragma unroll
        for (int it = 0; it < 2; it++) {
            int li  = it * 256 + tid;
            int row = li >> 3;
            int c4  = (li & 7) << 2;
            st_hilo_p(sb, sb + CA_TILE, row, c4, PK, ra[it]);
        }
#pragma unroll
        for (int it = 0; it < 4; it++) {
            int li  = it * 256 + tid;
            int row = li >> 5;
            int c4  = (li & 31) << 2;
            st_hilo_p(sb + 2*CA_TILE, sb + 2*CA_TILE + CB_TILE, row, c4, PN, rb[it]);
        }
    };

    load_regs(0);
    store_regs(0);
    __syncthreads();

    const int arow = lane & 15;
    const int kcol = (lane >> 4) << 3;

    for (int s = 0; s < 10; s++) {          // K = 320 = 10 * 32
        if (s < 9) load_regs(s + 1);
        const uint32_t sb = smb + (uint32_t)(s & 1) * CSTAGE;
        const uint32_t bB = sb + 2*CA_TILE;
#pragma unroll
        for (int ks = 0; ks < 2; ks++) {
            // B fragments via ldmatrix.trans on [k][n] tile
            uint32_t bh[2][4], bl[2][4];
#pragma unroll
            for (int p = 0; p < 2; p++) {
                int krow = ks * 16 + ((lane >> 3) & 1) * 8 + (lane & 7);
                int ncol = wn * 32 + (p * 2 + (lane >> 4)) * 8;
                uint32_t addr = bB + (uint32_t)(krow * PN + ncol) * 2u;
                ldm4t(addr,           bh[p]);
                ldm4t(addr + CB_TILE, bl[p]);
            }
            const uint32_t ab = sb + (uint32_t)((wm * 32 + arow) * PK + ks * 16 + kcol) * 2u;
#pragma unroll
            for (int i = 0; i < 2; i++) {
                uint32_t ah[4], al[4];
                ldm4(ab + (uint32_t)(i * 16 * PK * 2),           ah);
                ldm4(ab + (uint32_t)(i * 16 * PK * 2) + CA_TILE, al);
#pragma unroll
                for (int j = 0; j < 4; j++) {
                    uint32_t b0h = bh[j >> 1][(j & 1) * 2], b1h = bh[j >> 1][(j & 1) * 2 + 1];
                    mma_bf16(acc[i][j], ah, b0h, b1h);
                    mma_bf16(acc[i][j], al, b0h, b1h);
                    uint32_t b0l = bl[j >> 1][(j & 1) * 2], b1l = bl[j >> 1][(j & 1) * 2 + 1];
                    mma_bf16(acc[i][j], ah, b0l, b1l);
                }
            }
        }
        if (s < 9) store_regs(s + 1);
        __syncthreads();
    }

    const int r0b = t0 + wm * 32 + (lane >> 2);
    const int c0b = d0 + wn * 32 + ((lane & 3) << 1);
#pragma unroll
    for (int i = 0; i < 2; i++) {
#pragma unroll
        for (int j = 0; j < 4; j++) {
            int t  = r0b + i * 16;
            int dd = c0b + j * 8;
            *(float2*)(g_cell + ((size_t)b * T_ + t) * D_ + dd)       = make_float2(acc[i][j][0], acc[i][j][1]);
            *(float2*)(g_cell + ((size_t)b * T_ + t + 8) * D_ + dd)   = make_float2(acc[i][j][2], acc[i][j][3]);
        }
    }
}

// ------- scores[b,t,t'] = sum_d v[b,t,d] * tanh(cwm[b,t,d] + cm[b,t',d]) -------
__global__ void __launch_bounds__(256) scores_k(const float* __restrict__ v)
{
    __shared__ float sC[16][68];
    __shared__ float sV[16][68];
    __shared__ float sM[16][68];
    const int b  = blockIdx.z;
    const int t0 = blockIdx.y * 64;
    const int p0 = blockIdx.x * 64;
    const int tid = threadIdx.x;
    const int tx = tid & 15, ty = tid >> 4;
    const int row = tid >> 2;
    const int c4  = (tid & 3) << 2;

    float acc[4][4];
#pragma unroll
    for (int i = 0; i < 4; i++)
#pragma unroll
        for (int j = 0; j < 4; j++) acc[i][j] = 0.0f;

    const size_t baseT = ((size_t)b * T_ + t0 + row) * D_;
    const size_t baseP = ((size_t)b * T_ + p0 + row) * D_;

    for (int d0 = 0; d0 < D_; d0 += 16) {
        float4 cc = *(const float4*)(g_cwm + baseT + d0 + c4);
        float4 vv = *(const float4*)(v     + baseT + d0 + c4);
        float4 mm = *(const float4*)(g_cm  + baseP + d0 + c4);
        sC[c4+0][row]=cc.x; sC[c4+1][row]=cc.y; sC[c4+2][row]=cc.z; sC[c4+3][row]=cc.w;
        sV[c4+0][row]=vv.x; sV[c4+1][row]=vv.y; sV[c4+2][row]=vv.z; sV[c4+3][row]=vv.w;
        sM[c4+0][row]=mm.x; sM[c4+1][row]=mm.y; sM[c4+2][row]=mm.z; sM[c4+3][row]=mm.w;
        __syncthreads();
#pragma unroll
        for (int k = 0; k < 16; k++) {
            float a[4], av[4], bb[4];
            *(float4*)a  = *(const float4*)&sC[k][ty * 4];
            *(float4*)av = *(const float4*)&sV[k][ty * 4];
            *(float4*)bb = *(const float4*)&sM[k][tx * 4];
#pragma unroll
            for (int i = 0; i < 4; i++)
#pragma unroll
                for (int j = 0; j < 4; j++)
                    acc[i][j] = fmaf(av[i], tanh_fast(a[i] + bb[j]), acc[i][j]);
        }
        __syncthreads();
    }
#pragma unroll
    for (int i = 0; i < 4; i++) {
        size_t orow = ((size_t)b * T_ + t0 + ty * 4 + i) * T_ + p0 + tx * 4;
        *(float4*)(g_att + orow) = make_float4(acc[i][0], acc[i][1], acc[i][2], acc[i][3]);
    }
}

// ---------------- softmax over rows of length 320 ----------------
__global__ void __launch_bounds__(256) softmax_k()
{
    int w    = threadIdx.x >> 5;
    int lane = threadIdx.x & 31;
    int row  = blockIdx.x * 8 + w;
    float* p = g_att + (size_t)row * T_;
    float x[10];
#pragma unroll
    for (int i = 0; i < 10; i++) x[i] = p[i * 32 + lane];
    float m = x[0];
#pragma unroll
    for (int i = 1; i < 10; i++) m = fmaxf(m, x[i]);
#pragma unroll
    for (int o = 16; o > 0; o >>= 1) m = fmaxf(m, __shfl_xor_sync(0xffffffffu, m, o));
    float s = 0.0f;
#pragma unroll
    for (int i = 0; i < 10; i++) { x[i] = ex2f_((x[i] - m) * LOG2E); s += x[i]; }
#pragma unroll
    for (int o = 16; o > 0; o >>= 1) s += __shfl_xor_sync(0xffffffffu, s, o);
    float inv = rcpf_(s);
#pragma unroll
    for (int i = 0; i < 10; i++) p[i * 32 + lane] = x[i] * inv;
}

// ------- pack Whh -> [dir][gate][k4][h] as float4-of-k -------
__global__ void __launch_bounds__(256) pack_whh(const float* __restrict__ Wf,
                                               const float* __restrict__ Wb)
{
    int i = blockIdx.x * 256 + threadIdx.x;
    int dir = i / 49152;
    int r   = i % 49152;
    int g   = r / 16384;
    int k4  = (r >> 8) & 63;
    int h   = r & 255;
    const float* W = dir ? Wb : Wf;
    float4 val = *(const float4*)(W + (size_t)(g * 256 + h) * 256 + k4 * 4);
    ((float4*)g_Wpk)[i] = val;
}

// ------- pack [W1;W2] for the merged cwm/cm GEMM -------
__global__ void __launch_bounds__(256) pack_w12(const float* __restrict__ W1,
                                               const float* __restrict__ W2)
{
    int i = blockIdx.x * 256 + threadIdx.x;   // 131072 float4
    float4* dst = (float4*)g_W12;
    if (i < 65536) dst[i] = ((const float4*)W1)[i];
    else           dst[i] = ((const float4*)W2)[i - 65536];
}

// ---------------- persistent GRU recurrence, per-(dir,bb) group barriers ----------------
__device__ __forceinline__ void groupbar(int grp)
{
    __syncthreads();
    if (threadIdx.x == 0) {
        __threadfence();
        unsigned* cp = &g_cnt2[grp * 32];
        unsigned* gp = &g_gen2[grp * 32];
        unsigned g = *(volatile unsigned*)gp;
        unsigned a = atomicAdd(cp, 1u);
        if (a == 7u) {
            *cp = 0u;
            __threadfence();
            atomicAdd(gp, 1u);
        } else {
            while (*(volatile unsigned*)gp == g) { }
        }
        __threadfence();
    }
    __syncthreads();
}

__global__ void __launch_bounds__(256) recur_k(
    const float* __restrict__ gihf, const float* __restrict__ gihb,
    const float* __restrict__ bhhf, const float* __restrict__ bhhb,
    float* __restrict__ out)
{
    const int bid = blockIdx.x;
    const int dir = bid >> 6;
    const int hb  = (bid >> 3) & 7;
    const int bb  = bid & 7;
    const int grp = dir * 8 + bb;
    const int tid = threadIdx.x;
    const int hl  = tid & 31;
    const int bl  = tid >> 5;
    const int h   = hb * 32 + hl;
    const int b   = bb * 8 + bl;

    const float* gih = dir ? gihb : gihf;
    const float* bhh = dir ? bhhb : bhhf;
    const float bhr = bhh[h], bhz = bhh[256 + h], bhn = bhh[512 + h];

    __shared__ float sh[8 * 256];

    g_H[0][dir * 16384 + b * 256 + h] = 0.0f;
    groupbar(grp);

    int buf = 0;
    const float4* Wbase = (const float4*)g_Wpk + (size_t)dir * 3 * 64 * 256;
    const float4* wr = Wbase + 0 * 16384 + h;
    const float4* wz = Wbase + 1 * 16384 + h;
    const float4* wn = Wbase + 2 * 16384 + h;

    for (int t = 0; t < T_; t++) {
        {
            const float4* src = (const float4*)(g_H[buf] + dir * 16384 + bb * 8 * 256);
            float4* dst = (float4*)sh;
            dst[tid]       = __ldcg(src + tid);
            dst[tid + 256] = __ldcg(src + tid + 256);
        }
        __syncthreads();

        float ar = 0.0f, az = 0.0f, an = 0.0f;
        const float4* hv = (const float4*)(sh + bl * 256);
#pragma unroll 4
        for (int k4 = 0; k4 < 64; k4++) {
            float4 h4 = hv[k4];
            float4 a = wr[(size_t)k4 * 256];
            float4 c = wz[(size_t)k4 * 256];
            float4 d = wn[(size_t)k4 * 256];
            ar = fmaf(a.x,h4.x, fmaf(a.y,h4.y, fmaf(a.z,h4.z, fmaf(a.w,h4.w, ar))));
            az = fmaf(c.x,h4.x, fmaf(c.y,h4.y, fmaf(c.z,h4.z, fmaf(c.w,h4.w, az))));
            an = fmaf(d.x,h4.x, fmaf(d.y,h4.y, fmaf(d.z,h4.z, fmaf(d.w,h4.w, an))));
        }

        size_t gb = ((size_t)b * T_ + t) * 768;
        float ir = gih[gb + h], iz = gih[gb + 256 + h], in_ = gih[gb + 512 + h];
        float r = sigm_fast(ir + ar + bhr);
        float z = sigm_fast(iz + az + bhz);
        float n = tanh_fast(in_ + r * (an + bhn));
        float hp = sh[bl * 256 + h];
        float hn = (1.0f - z) * n + z * hp;

        g_H[buf ^ 1][dir * 16384 + b * 256 + h] = hn;
        out[((size_t)t * B_ + b) * 512 + dir * 256 + h] = hn;
        buf ^= 1;
        groupbar(grp);
    }
}

// ---------------- launcher ----------------
extern "C" void kernel_launch(void* const* d_in, const int* in_sizes, int n_in,
                              void* d_out, int out_size)
{
    const float* v     = (const float*)d_in[0];
    const float* W1    = (const float*)d_in[1];
    const float* b1    = (const float*)d_in[2];
    const float* W2    = (const float*)d_in[3];
    const float* b2    = (const float*)d_in[4];
    const float* Wg    = (const float*)d_in[5];
    const float* bg    = (const float*)d_in[6];
    const float* Wih_f = (const float*)d_in[7];
    const float* Whh_f = (const float*)d_in[8];
    const float* bih_f = (const float*)d_in[9];
    const float* bhh_f = (const float*)d_in[10];
    const float* Wih_b = (const float*)d_in[11];
    const float* Whh_b = (const float*)d_in[12];
    const float* bih_b = (const float*)d_in[13];
    const float* bhh_b = (const float*)d_in[14];
    float* out = (float*)d_out;

    float *p_cwm, *p_cm, *p_cell, *p_gi, *p_gihf, *p_gihb, *p_W12;
    cudaGetSymbolAddress((void**)&p_cwm,  g_cwm);
    cudaGetSymbolAddress((void**)&p_cm,   g_cm);
    cudaGetSymbolAddress((void**)&p_cell, g_cell);
    cudaGetSymbolAddress((void**)&p_gi,   g_gi);
    cudaGetSymbolAddress((void**)&p_gihf, g_gihf);
    cudaGetSymbolAddress((void**)&p_gihb, g_gihb);
    cudaGetSymbolAddress((void**)&p_W12,  g_W12);

    cudaFuncSetAttribute(gemm_tc, cudaFuncAttributeMaxDynamicSharedMemorySize, GSM_TOTAL);
    cudaFuncSetAttribute(cell_tc, cudaFuncAttributeMaxDynamicSharedMemorySize, CSM_TOTAL);

    pack_whh<<<384, 256>>>(Whh_f, Whh_b);
    pack_w12<<<512, 256>>>(W1, W2);

    // merged: [cwm | cm] = v @ [W1;W2]^T, split-output epilogue
    gemm_tc<<<dim3(8, 160), 256, GSM_TOTAL>>>(v, nullptr, p_W12, b1, b2, nullptr, nullptr,
                                              p_cwm, p_cm, 1024, 512, 2);

    scores_k<<<dim3(5, 5, B_), 256>>>(v);
    softmax_k<<<2560, 256>>>();
    cell_tc<<<dim3(4, 5, B_), 256, CSM_TOTAL>>>(v);

    // gi = pg * sigmoid(pg @ Wg^T + bg), pg = [v | cell]
    gemm_tc<<<dim3(8, 160), 256, GSM_TOTAL>>>(v, p_cell, Wg, bg, nullptr, v, p_cell,
                                              p_gi, nullptr, 1024, 1024, 1);

    // gih_{f,b} = gi @ Wih^T + bih
    gemm_tc<<<dim3(6, 160), 256, GSM_TOTAL>>>(p_gi, nullptr, Wih_f, bih_f, nullptr, nullptr, nullptr,
                                              p_gihf, nullptr, 768, 1024, 0);
    gemm_tc<<<dim3(6, 160), 256, GSM_TOTAL>>>(p_gi, nullptr, Wih_b, bih_b, nullptr, nullptr, nullptr,
                                              p_gihb, nullptr, 768, 1024, 0);

    recur_k<<<128, 256>>>(p_gihf, p_gihb, bhh_f, bhh_b, out);
}

// round 15
// speedup vs baseline: 1.3893x; 1.0339x over previous
#include <cuda_runtime.h>
#include <cuda_bf16.h>
#include <cstdint>
#include <cstddef>

#define B_ 64
#define T_ 320
#define H_ 256
#define D_ 512
#define NR (B_*T_)   // 20480

// ---------------- device scratch ----------------
static __device__ float g_cwm [(size_t)NR*D_];
static __device__ float g_cm  [(size_t)NR*D_];
static __device__ float g_att [(size_t)B_*T_*T_];          // fp32 scores
static __device__ float g_cell[(size_t)NR*D_];
static __device__ float g_gih [(size_t)NR*1536];           // merged f|b
static __device__ float g_Wpk [(size_t)2*3*64*256*4];
static __device__ float g_H   [2][2*B_*H_];
static __device__ unsigned g_cnt2[16*32];
static __device__ unsigned g_gen2[16*32];
static __device__ unsigned g_flag[16][8*32];

// bf16 hi/lo operand planes
static __device__ __nv_bfloat16 g_vh [(size_t)NR*D_],      g_vl [(size_t)NR*D_];
static __device__ __nv_bfloat16 g_ath[(size_t)B_*T_*T_],   g_atl[(size_t)B_*T_*T_];
static __device__ __nv_bfloat16 g_ch [(size_t)NR*D_],      g_cl [(size_t)NR*D_];
static __device__ __nv_bfloat16 g_gph[(size_t)NR*1024],    g_gpl[(size_t)NR*1024];
static __device__ __nv_bfloat16 g_w12h[(size_t)1024*512],  g_w12l[(size_t)1024*512];
static __device__ __nv_bfloat16 g_wgh [(size_t)1024*1024], g_wgl [(size_t)1024*1024];
static __device__ __nv_bfloat16 g_wihh[(size_t)1536*1024], g_wihl[(size_t)1536*1024];

// ---------------- fast transcendentals ----------------
__device__ __forceinline__ float ex2f_(float x){ float y; asm("ex2.approx.ftz.f32 %0, %1;" : "=f"(y) : "f"(x)); return y; }
__device__ __forceinline__ float rcpf_(float x){ float y; asm("rcp.approx.ftz.f32 %0, %1;" : "=f"(y) : "f"(x)); return y; }
#define LOG2E 1.4426950408889634f
__device__ __forceinline__ float tanh_fast(float x){
    float t = ex2f_(x * (2.0f*LOG2E));
    return fmaf(-2.0f, rcpf_(t + 1.0f), 1.0f);
}
__device__ __forceinline__ float sigm_fast(float x){
    return rcpf_(1.0f + ex2f_(-x * LOG2E));
}

__device__ __forceinline__ uint32_t smem_u32(const void* p){
    uint32_t a;
    asm("{ .reg .u64 t; cvta.to.shared.u64 t, %1; cvt.u32.u64 %0, t; }" : "=r"(a) : "l"(p));
    return a;
}

// ---------------- HMMA helpers ----------------
__device__ __forceinline__ void ldm4(uint32_t a, uint32_t* r){
    asm volatile("ldmatrix.sync.aligned.m8n8.x4.shared.b16 {%0,%1,%2,%3}, [%4];"
        : "=r"(r[0]), "=r"(r[1]), "=r"(r[2]), "=r"(r[3]) : "r"(a));
}
__device__ __forceinline__ void ldm4t(uint32_t a, uint32_t* r){
    asm volatile("ldmatrix.sync.aligned.m8n8.x4.trans.shared.b16 {%0,%1,%2,%3}, [%4];"
        : "=r"(r[0]), "=r"(r[1]), "=r"(r[2]), "=r"(r[3]) : "r"(a));
}
__device__ __forceinline__ void mma_bf16(float* c, const uint32_t* a, uint32_t b0, uint32_t b1){
    asm volatile("mma.sync.aligned.m16n8k16.row.col.f32.bf16.bf16.f32 "
        "{%0,%1,%2,%3}, {%4,%5,%6,%7}, {%8,%9}, {%0,%1,%2,%3};"
        : "+f"(c[0]), "+f"(c[1]), "+f"(c[2]), "+f"(c[3])
        : "r"(a[0]), "r"(a[1]), "r"(a[2]), "r"(a[3]), "r"(b0), "r"(b1));
}
__device__ __forceinline__ void sts2(uint32_t addr, uint2 v){
    asm volatile("st.shared.v2.b32 [%0], {%1, %2};" :: "r"(addr), "r"(v.x), "r"(v.y) : "memory");
}

// ---------------- fp32 -> bf16 hi/lo plane split ----------------
__global__ void __launch_bounds__(256) split_k(const float4* __restrict__ src,
                                              __nv_bfloat162* __restrict__ hi,
                                              __nv_bfloat162* __restrict__ lo, int n4)
{
    int i = blockIdx.x * 256 + threadIdx.x;
    if (i >= n4) return;
    float4 f = src[i];
    __nv_bfloat162 h01 = __floats2bfloat162_rn(f.x, f.y);
    __nv_bfloat162 h23 = __floats2bfloat162_rn(f.z, f.w);
    float2 a = __bfloat1622float2(h01);
    float2 b = __bfloat1622float2(h23);
    hi[2*i]   = h01;
    hi[2*i+1] = h23;
    lo[2*i]   = __floats2bfloat162_rn(f.x - a.x, f.y - a.y);
    lo[2*i+1] = __floats2bfloat162_rn(f.z - b.x, f.w - b.y);
}

// ===================== gemm_tc: C = A @ B^T (+bias) — HMMA, pre-split bf16 hi/lo =====================
// grid (N/128, M/128).  A1h != null: A virtual [A0|A1] split at k=512 (row stride 512 each).
// mode 0: C[row*N+col] = acc (+bias[col] if bias)
// mode 1: planes Ch/Cl <- P[:,col] * sigmoid(acc + bias[col])  (P0 cols<512, P1 cols>=512)
// mode 2: split fp32: col<512 -> C (+bias), col>=512 -> C2 (+bias2); both row-stride 512
#define PK 40
#define TILE_B (128*PK*2)
#define STAGE_B (4*TILE_B)
#define GSM_TOTAL (2*STAGE_B)
__global__ void __launch_bounds__(256) gemm_tc(
    const __nv_bfloat16* __restrict__ A0h, const __nv_bfloat16* __restrict__ A0l,
    const __nv_bfloat16* __restrict__ A1h, const __nv_bfloat16* __restrict__ A1l,
    const __nv_bfloat16* __restrict__ Bph, const __nv_bfloat16* __restrict__ Bpl,
    const float* __restrict__ bias, const float* __restrict__ bias2,
    const float* __restrict__ P0, const float* __restrict__ P1,
    float* __restrict__ C, float* __restrict__ C2,
    __nv_bfloat16* __restrict__ Ch, __nv_bfloat16* __restrict__ Cl,
    int N, int K, int mode)
{
    extern __shared__ char sm[];
    const uint32_t smb = smem_u32(sm);
    const int tid  = threadIdx.x;
    const int bm   = blockIdx.y * 128;
    const int bn   = blockIdx.x * 128;
    const int lane = tid & 31;
    const int wid  = tid >> 5;
    const int wm   = wid & 1;
    const int wn   = wid >> 1;
    const int nst  = K >> 5;

    float acc[4][4][4];
#pragma unroll
    for (int i = 0; i < 4; i++)
#pragma unroll
        for (int j = 0; j < 4; j++)
#pragma unroll
            for (int q = 0; q < 4; q++) acc[i][j][q] = 0.0f;

    const int arow = lane & 15;
    const int kcol = (lane >> 4) << 3;

    uint2 rah[4], ral[4], rbh[4], rbl[4];
    auto load_regs = [&](int s){
        const int kbase = s << 5;
#pragma unroll
        for (int it = 0; it < 4; it++) {
            int li  = it * 256 + tid;
            int row = li >> 3;
            int c4  = (li & 7) << 2;
            int kg  = kbase + c4;
            const __nv_bfloat16 *ph, *pl;
            if (A1h) {
                if (kg < 512) { ph = A0h + (size_t)(bm + row) * 512 + kg;
                                pl = A0l + (size_t)(bm + row) * 512 + kg; }
                else          { ph = A1h + (size_t)(bm + row) * 512 + (kg - 512);
                                pl = A1l + (size_t)(bm + row) * 512 + (kg - 512); }
            } else {
                ph = A0h + (size_t)(bm + row) * K + kg;
                pl = A0l + (size_t)(bm + row) * K + kg;
            }
            rah[it] = *(const uint2*)ph;
            ral[it] = *(const uint2*)pl;
            rbh[it] = *(const uint2*)(Bph + (size_t)(bn + row) * K + kg);
            rbl[it] = *(const uint2*)(Bpl + (size_t)(bn + row) * K + kg);
        }
    };
    auto store_regs = [&](int s){
        uint32_t sb = smb + (uint32_t)(s & 1) * STAGE_B;
#pragma unroll
        for (int it = 0; it < 4; it++) {
            int li  = it * 256 + tid;
            int row = li >> 3;
            int c4  = (li & 7) << 2;
            uint32_t off = (uint32_t)(row * PK + c4) * 2u;
            sts2(sb + off,            rah[it]);
            sts2(sb + TILE_B + off,   ral[it]);
            sts2(sb + 2*TILE_B + off, rbh[it]);
            sts2(sb + 3*TILE_B + off, rbl[it]);
        }
    };

    load_regs(0);
    store_regs(0);
    __syncthreads();

    for (int s = 0; s < nst; s++) {
        if (s + 1 < nst) load_regs(s + 1);
        const uint32_t sb = smb + (uint32_t)(s & 1) * STAGE_B;
#pragma unroll
        for (int ks = 0; ks < 2; ks++) {
            const int k0 = ks << 4;
            uint32_t bh[2][4], bl[2][4];
            {
                uint32_t bb = sb + 2*TILE_B + (uint32_t)((wn * 32 + arow) * PK + k0 + kcol) * 2u;
                ldm4(bb,              bh[0]);
                ldm4(bb + 16*PK*2,    bh[1]);
                ldm4(bb + TILE_B,           bl[0]);
                ldm4(bb + TILE_B + 16*PK*2, bl[1]);
            }
            const uint32_t ab = sb + (uint32_t)((wm * 64 + arow) * PK + k0 + kcol) * 2u;
#pragma unroll
            for (int i = 0; i < 4; i++) {
                uint32_t ah[4], al[4];
                ldm4(ab + (uint32_t)(i * 16 * PK * 2),          ah);
                ldm4(ab + (uint32_t)(i * 16 * PK * 2) + TILE_B, al);
#pragma unroll
                for (int j = 0; j < 4; j++) {
                    uint32_t b0h = bh[j >> 1][j & 1], b1h = bh[j >> 1][(j & 1) + 2];
                    mma_bf16(acc[i][j], ah, b0h, b1h);
                    mma_bf16(acc[i][j], al, b0h, b1h);
                    uint32_t b0l = bl[j >> 1][j & 1], b1l = bl[j >> 1][(j & 1) + 2];
                    mma_bf16(acc[i][j], ah, b0l, b1l);
                }
            }
        }
        if (s + 1 < nst) store_regs(s + 1);
        __syncthreads();
    }

    const int r0b = bm + wm * 64 + (lane >> 2);
    const int c0b = bn + wn * 32 + ((lane & 3) << 1);
#pragma unroll
    for (int i = 0; i < 4; i++) {
#pragma unroll
        for (int j = 0; j < 4; j++) {
            int row = r0b + i * 16;
            int col = c0b + j * 8;
            float* Co = C;
            const float* bp = bias;
            int colo = col, stride = N;
            if (mode == 2) {
                stride = 512;
                if (col >= 512) { Co = C2; bp = bias2; colo = col - 512; }
            }
            float bz0 = bp ? bp[colo]     : 0.0f;
            float bz1 = bp ? bp[colo + 1] : 0.0f;
            float o0 = acc[i][j][0] + bz0;
            float o1 = acc[i][j][1] + bz1;
            float o2 = acc[i][j][2] + bz0;
            float o3 = acc[i][j][3] + bz1;
            if (mode == 1) {
                const float* P = (col < 512) ? P0 : P1;
                int cc = (col < 512) ? col : col - 512;
                float2 p0 = *(const float2*)(P + (size_t)row * 512 + cc);
                float2 p1 = *(const float2*)(P + (size_t)(row + 8) * 512 + cc);
                o0 = p0.x * sigm_fast(o0); o1 = p0.y * sigm_fast(o1);
                o2 = p1.x * sigm_fast(o2); o3 = p1.y * sigm_fast(o3);
                // emit bf16 hi/lo planes (gi)
                __nv_bfloat162 h01 = __floats2bfloat162_rn(o0, o1);
                float2 hf = __bfloat1622float2(h01);
                __nv_bfloat162 l01 = __floats2bfloat162_rn(o0 - hf.x, o1 - hf.y);
                __nv_bfloat162 h23 = __floats2bfloat162_rn(o2, o3);
                float2 hg = __bfloat1622float2(h23);
                __nv_bfloat162 l23 = __floats2bfloat162_rn(o2 - hg.x, o3 - hg.y);
                *(__nv_bfloat162*)(Ch + (size_t)row * N + col)       = h01;
                *(__nv_bfloat162*)(Cl + (size_t)row * N + col)       = l01;
                *(__nv_bfloat162*)(Ch + (size_t)(row + 8) * N + col) = h23;
                *(__nv_bfloat162*)(Cl + (size_t)(row + 8) * N + col) = l23;
            } else {
                *(float2*)(Co + (size_t)row * stride + colo)       = make_float2(o0, o1);
                *(float2*)(Co + (size_t)(row + 8) * stride + colo) = make_float2(o2, o3);
            }
        }
    }
}

// ===================== cell_tc: cell[b,t,d] = attn[b,t,:] @ v[b,:,d] (HMMA, planes) =====================
#define PN 136
#define CA_TILE (64*PK*2)
#define CB_TILE (32*PN*2)
#define CSTAGE (2*CA_TILE + 2*CB_TILE)
#define CSM_TOTAL (2*CSTAGE)
__global__ void __launch_bounds__(256) cell_tc()
{
    extern __shared__ char sm[];
    const uint32_t smb = smem_u32(sm);
    const int tid  = threadIdx.x;
    const int b    = blockIdx.z;
    const int t0   = blockIdx.y * 64;
    const int d0   = blockIdx.x * 128;
    const int lane = tid & 31;
    const int wid  = tid >> 5;
    const int wm   = wid & 1;
    const int wn   = wid >> 1;

    const __nv_bfloat16* ath = g_ath + (size_t)b * T_ * T_;
    const __nv_bfloat16* atl = g_atl + (size_t)b * T_ * T_;
    const __nv_bfloat16* vph = g_vh  + (size_t)b * T_ * D_;
    const __nv_bfloat16* vpl = g_vl  + (size_t)b * T_ * D_;

    float acc[2][4][4];
#pragma unroll
    for (int i = 0; i < 2; i++)
#pragma unroll
        for (int j = 0; j < 4; j++)
#pragma unroll
            for (int q = 0; q < 4; q++) acc[i][j][q] = 0.0f;

    uint2 rah[2], ral[2], rbh[4], rbl[4];
    auto load_regs = [&](int s){
        const int k0 = s << 5;
#pragma unroll
        for (int it = 0; it < 2; it++) {
            int li  = it * 256 + tid;
            int row = li >> 3;
            int c4  = (li & 7) << 2;
            rah[it] = *(const uint2*)(ath + (size_t)(t0 + row) * T_ + k0 + c4);
            ral[it] = *(const uint2*)(atl + (size_t)(t0 + row) * T_ + k0 + c4);
        }
#pragma unroll
        for (int it = 0; it < 4; it++) {
            int li  = it * 256 + tid;
            int row = li >> 5;
            int c4  = (li & 31) << 2;
            rbh[it] = *(const uint2*)(vph + (size_t)(k0 + row) * D_ + d0 + c4);
            rbl[it] = *(const uint2*)(vpl + (size_t)(k0 + row) * D_ + d0 + c4);
        }
    };
    auto store_regs = [&](int s){
        uint32_t sb = smb + (uint32_t)(s & 1) * CSTAGE;
#pragma unroll
        for (int it = 0; it < 2; it++) {
            int li  = it * 256 + tid;
            int row = li >> 3;
            int c4  = (li & 7) << 2;
            uint32_t off = (uint32_t)(row * PK + c4) * 2u;
            sts2(sb + off,           rah[it]);
            sts2(sb + CA_TILE + off, ral[it]);
        }
#pragma unroll
        for (int it = 0; it < 4; it++) {
            int li  = it * 256 + tid;
            int row = li >> 5;
            int c4  = (li & 31) << 2;
            uint32_t off = (uint32_t)(row * PN + c4) * 2u;
            sts2(sb + 2*CA_TILE + off,           rbh[it]);
            sts2(sb + 2*CA_TILE + CB_TILE + off, rbl[it]);
        }
    };

    load_regs(0);
    store_regs(0);
    __syncthreads();

    const int arow = lane & 15;
    const int kcol = (lane >> 4) << 3;

    for (int s = 0; s < 10; s++) {
        if (s < 9) load_regs(s + 1);
        const uint32_t sb = smb + (uint32_t)(s & 1) * CSTAGE;
        const uint32_t bB = sb + 2*CA_TILE;
#pragma unroll
        for (int ks = 0; ks < 2; ks++) {
            uint32_t bh[2][4], bl[2][4];
#pragma unroll
            for (int p = 0; p < 2; p++) {
                int krow = ks * 16 + ((lane >> 3) & 1) * 8 + (lane & 7);
                int ncol = wn * 32 + (p * 2 + (lane >> 4)) * 8;
                uint32_t addr = bB + (uint32_t)(krow * PN + ncol) * 2u;
                ldm4t(addr,           bh[p]);
                ldm4t(addr + CB_TILE, bl[p]);
            }
            const uint32_t ab = sb + (uint32_t)((wm * 32 + arow) * PK + ks * 16 + kcol) * 2u;
#pragma unroll
            for (int i = 0; i < 2; i++) {
                uint32_t ah[4], al[4];
                ldm4(ab + (uint32_t)(i * 16 * PK * 2),           ah);
                ldm4(ab + (uint32_t)(i * 16 * PK * 2) + CA_TILE, al);
#pragma unroll
                for (int j = 0; j < 4; j++) {
                    uint32_t b0h = bh[j >> 1][(j & 1) * 2], b1h = bh[j >> 1][(j & 1) * 2 + 1];
                    mma_bf16(acc[i][j], ah, b0h, b1h);
                    mma_bf16(acc[i][j], al, b0h, b1h);
                    uint32_t b0l = bl[j >> 1][(j & 1) * 2], b1l = bl[j >> 1][(j & 1) * 2 + 1];
                    mma_bf16(acc[i][j], ah, b0l, b1l);
                }
            }
        }
        if (s < 9) store_regs(s + 1);
        __syncthreads();
    }

    const int r0b = t0 + wm * 32 + (lane >> 2);
    const int c0b = d0 + wn * 32 + ((lane & 3) << 1);
#pragma unroll
    for (int i = 0; i < 2; i++) {
#pragma unroll
        for (int j = 0; j < 4; j++) {
            int t  = r0b + i * 16;
            int dd = c0b + j * 8;
#pragma unroll
            for (int rr = 0; rr < 2; rr++) {
                float o0 = acc[i][j][rr * 2 + 0];
                float o1 = acc[i][j][rr * 2 + 1];
                size_t idx = ((size_t)b * T_ + t + rr * 8) * D_ + dd;
                *(float2*)(g_cell + idx) = make_float2(o0, o1);
                __nv_bfloat162 h01 = __floats2bfloat162_rn(o0, o1);
                float2 hf = __bfloat1622float2(h01);
                *(__nv_bfloat162*)(g_ch + idx) = h01;
                *(__nv_bfloat162*)(g_cl + idx) = __floats2bfloat162_rn(o0 - hf.x, o1 - hf.y);
            }
        }
    }
}

// ------- scores[b,t,t'] = sum_d v[b,t,d] * tanh(cwm[b,t,d] + cm[b,t',d]) -------
__global__ void __launch_bounds__(256) scores_k(const float* __restrict__ v)
{
    __shared__ float sC[16][68];
    __shared__ float sV[16][68];
    __shared__ float sM[16][68];
    const int b  = blockIdx.z;
    const int t0 = blockIdx.y * 64;
    const int p0 = blockIdx.x * 64;
    const int tid = threadIdx.x;
    const int tx = tid & 15, ty = tid >> 4;
    const int row = tid >> 2;
    const int c4  = (tid & 3) << 2;

    float acc[4][4];
#pragma unroll
    for (int i = 0; i < 4; i++)
#pragma unroll
        for (int j = 0; j < 4; j++) acc[i][j] = 0.0f;

    const size_t baseT = ((size_t)b * T_ + t0 + row) * D_;
    const size_t baseP = ((size_t)b * T_ + p0 + row) * D_;

    for (int d0 = 0; d0 < D_; d0 += 16) {
        float4 cc = *(const float4*)(g_cwm + baseT + d0 + c4);
        float4 vv = *(const float4*)(v     + baseT + d0 + c4);
        float4 mm = *(const float4*)(g_cm  + baseP + d0 + c4);
        sC[c4+0][row]=cc.x; sC[c4+1][row]=cc.y; sC[c4+2][row]=cc.z; sC[c4+3][row]=cc.w;
        sV[c4+0][row]=vv.x; sV[c4+1][row]=vv.y; sV[c4+2][row]=vv.z; sV[c4+3][row]=vv.w;
        sM[c4+0][row]=mm.x; sM[c4+1][row]=mm.y; sM[c4+2][row]=mm.z; sM[c4+3][row]=mm.w;
        __syncthreads();
#pragma unroll
        for (int k = 0; k < 16; k++) {
            float a[4], av[4], bb[4];
            *(float4*)a  = *(const float4*)&sC[k][ty * 4];
            *(float4*)av = *(const float4*)&sV[k][ty * 4];
            *(float4*)bb = *(const float4*)&sM[k][tx * 4];
#pragma unroll
            for (int i = 0; i < 4; i++)
#pragma unroll
                for (int j = 0; j < 4; j++)
                    acc[i][j] = fmaf(av[i], tanh_fast(a[i] + bb[j]), acc[i][j]);
        }
        __syncthreads();
    }
#pragma unroll
    for (int i = 0; i < 4; i++) {
        size_t orow = ((size_t)b * T_ + t0 + ty * 4 + i) * T_ + p0 + tx * 4;
        *(float4*)(g_att + orow) = make_float4(acc[i][0], acc[i][1], acc[i][2], acc[i][3]);
    }
}

// ---------------- softmax over rows of 320 -> bf16 hi/lo attn planes ----------------
__global__ void __launch_bounds__(256) softmax_k()
{
    int w    = threadIdx.x >> 5;
    int lane = threadIdx.x & 31;
    int row  = blockIdx.x * 8 + w;
    const float* p = g_att + (size_t)row * T_;
    __nv_bfloat16* ph = g_ath + (size_t)row * T_;
    __nv_bfloat16* pl = g_atl + (size_t)row * T_;
    float x[10];
#pragma unroll
    for (int i = 0; i < 10; i++) x[i] = p[i * 32 + lane];
    float m = x[0];
#pragma unroll
    for (int i = 1; i < 10; i++) m = fmaxf(m, x[i]);
#pragma unroll
    for (int o = 16; o > 0; o >>= 1) m = fmaxf(m, __shfl_xor_sync(0xffffffffu, m, o));
    float s = 0.0f;
#pragma unroll
    for (int i = 0; i < 10; i++) { x[i] = ex2f_((x[i] - m) * LOG2E); s += x[i]; }
#pragma unroll
    for (int o = 16; o > 0; o >>= 1) s += __shfl_xor_sync(0xffffffffu, s, o);
    float inv = rcpf_(s);
#pragma unroll
    for (int i = 0; i < 10; i++) {
        float val = x[i] * inv;
        __nv_bfloat16 h = __float2bfloat16_rn(val);
        ph[i * 32 + lane] = h;
        pl[i * 32 + lane] = __float2bfloat16_rn(val - __bfloat162float(h));
    }
}

// ------- pack Whh -> [dir][gate][k4][h] as float4-of-k -------
__global__ void __launch_bounds__(256) pack_whh(const float* __restrict__ Wf,
                                               const float* __restrict__ Wb)
{
    int i = blockIdx.x * 256 + threadIdx.x;
    int dir = i / 49152;
    int r   = i % 49152;
    int g   = r / 16384;
    int k4  = (r >> 8) & 63;
    int h   = r & 255;
    const float* W = dir ? Wb : Wf;
    float4 val = *(const float4*)(W + (size_t)(g * 256 + h) * 256 + k4 * 4);
    ((float4*)g_Wpk)[i] = val;
}

// ---------------- persistent GRU recurrence ----------------
__device__ __forceinline__ void groupbar_atomic(int grp)
{
    __syncthreads();
    if (threadIdx.x == 0) {
        __threadfence();
        unsigned* cp = &g_cnt2[grp * 32];
        unsigned* gp = &g_gen2[grp * 32];
        unsigned g = *(volatile unsigned*)gp;
        unsigned a = atomicAdd(cp, 1u);
        if (a == 7u) {
            *cp = 0u;
            __threadfence();
            atomicAdd(gp, 1u);
        } else {
            while (*(volatile unsigned*)gp == g) { }
        }
        __threadfence();
    }
    __syncthreads();
}

__global__ void __launch_bounds__(256) recur_k(
    const float* __restrict__ gih,
    const float* __restrict__ bihf, const float* __restrict__ bhhf,
    const float* __restrict__ bihb, const float* __restrict__ bhhb,
    float* __restrict__ out)
{
    const int bid = blockIdx.x;
    const int dir = bid >> 6;
    const int hb  = (bid >> 3) & 7;
    const int bb  = bid & 7;
    const int grp = dir * 8 + bb;
    const int tid = threadIdx.x;
    const int hl  = tid & 31;
    const int bl  = tid >> 5;
    const int h   = hb * 32 + hl;
    const int b   = bb * 8 + bl;

    const float* bih = dir ? bihb : bihf;
    const float* bhh = dir ? bhhb : bhhf;
    const float bhr = bih[h]       + bhh[h];
    const float bhz = bih[256 + h] + bhh[256 + h];
    const float bin = bih[512 + h];
    const float bhn = bhh[512 + h];

    __shared__ float sh[8 * 256];

    if (tid == 0) *(volatile unsigned*)&g_flag[grp][hb * 32] = 0u;
    g_H[0][dir * 16384 + b * 256 + h] = 0.0f;
    groupbar_atomic(grp);

    int buf = 0;
    const float4* Wbase = (const float4*)g_Wpk + (size_t)dir * 3 * 64 * 256;
    const float4* wr = Wbase + 0 * 16384 + h;
    const float4* wz = Wbase + 1 * 16384 + h;
    const float4* wn = Wbase + 2 * 16384 + h;

    for (int t = 0; t < T_; t++) {
        {
            const float4* src = (const float4*)(g_H[buf] + dir * 16384 + bb * 8 * 256);
            float4* dst = (float4*)sh;
            dst[tid]       = __ldcg(src + tid);
            dst[tid + 256] = __ldcg(src + tid + 256);
        }
        __syncthreads();

        float ar = 0.0f, az = 0.0f, an = 0.0f;
        const float4* hv = (const float4*)(sh + bl * 256);
#pragma unroll 4
        for (int k4 = 0; k4 < 64; k4++) {
            float4 h4 = hv[k4];
            float4 a = wr[(size_t)k4 * 256];
            float4 c = wz[(size_t)k4 * 256];
            float4 d = wn[(size_t)k4 * 256];
            ar = fmaf(a.x,h4.x, fmaf(a.y,h4.y, fmaf(a.z,h4.z, fmaf(a.w,h4.w, ar))));
            az = fmaf(c.x,h4.x, fmaf(c.y,h4.y, fmaf(c.z,h4.z, fmaf(c.w,h4.w, az))));
            an = fmaf(d.x,h4.x, fmaf(d.y,h4.y, fmaf(d.z,h4.z, fmaf(d.w,h4.w, an))));
        }

        size_t gb = ((size_t)b * T_ + t) * 1536 + (size_t)dir * 768;
        float ir  = gih[gb + h];
        float iz  = gih[gb + 256 + h];
        float in_ = gih[gb + 512 + h] + bin;
        float r = sigm_fast(ir + ar + bhr);
        float z = sigm_fast(iz + az + bhz);
        float n = tanh_fast(in_ + r * (an + bhn));
        float hp = sh[bl * 256 + h];
        float hn = (1.0f - z) * n + z * hp;

        g_H[buf ^ 1][dir * 16384 + b * 256 + h] = hn;
        out[((size_t)t * B_ + b) * 512 + dir * 256 + h] = hn;
        buf ^= 1;

        // flag-based group barrier
        __syncthreads();
        if (tid == 0) {
            __threadfence();
            *(volatile unsigned*)&g_flag[grp][hb * 32] = (unsigned)(t + 1);
        }
        if (tid < 8) {
            unsigned tgt = (unsigned)(t + 1);
            unsigned vv;
            do {
                asm volatile("ld.acquire.gpu.u32 %0, [%1];"
                             : "=r"(vv) : "l"(&g_flag[grp][tid * 32]) : "memory");
            } while (vv < tgt);
        }
        __syncthreads();
    }
}

// ---------------- launcher ----------------
extern "C" void kernel_launch(void* const* d_in, const int* in_sizes, int n_in,
                              void* d_out, int out_size)
{
    const float* v     = (const float*)d_in[0];
    const float* W1    = (const float*)d_in[1];
    const float* b1    = (const float*)d_in[2];
    const float* W2    = (const float*)d_in[3];
    const float* b2    = (const float*)d_in[4];
    const float* Wg    = (const float*)d_in[5];
    const float* bg    = (const float*)d_in[6];
    const float* Wih_f = (const float*)d_in[7];
    const float* Whh_f = (const float*)d_in[8];
    const float* bih_f = (const float*)d_in[9];
    const float* bhh_f = (const float*)d_in[10];
    const float* Wih_b = (const float*)d_in[11];
    const float* Whh_b = (const float*)d_in[12];
    const float* bih_b = (const float*)d_in[13];
    const float* bhh_b = (const float*)d_in[14];
    float* out = (float*)d_out;

    float *p_cwm, *p_cm, *p_cell, *p_gih;
    __nv_bfloat16 *p_vh, *p_vl, *p_ch, *p_cl, *p_gph, *p_gpl;
    __nv_bfloat16 *p_w12h, *p_w12l, *p_wgh, *p_wgl, *p_wihh, *p_wihl;
    cudaGetSymbolAddress((void**)&p_cwm,  g_cwm);
    cudaGetSymbolAddress((void**)&p_cm,   g_cm);
    cudaGetSymbolAddress((void**)&p_cell, g_cell);
    cudaGetSymbolAddress((void**)&p_gih,  g_gih);
    cudaGetSymbolAddress((void**)&p_vh,   g_vh);
    cudaGetSymbolAddress((void**)&p_vl,   g_vl);
    cudaGetSymbolAddress((void**)&p_ch,   g_ch);
    cudaGetSymbolAddress((void**)&p_cl,   g_cl);
    cudaGetSymbolAddress((void**)&p_gph,  g_gph);
    cudaGetSymbolAddress((void**)&p_gpl,  g_gpl);
    cudaGetSymbolAddress((void**)&p_w12h, g_w12h);
    cudaGetSymbolAddress((void**)&p_w12l, g_w12l);
    cudaGetSymbolAddress((void**)&p_wgh,  g_wgh);
    cudaGetSymbolAddress((void**)&p_wgl,  g_wgl);
    cudaGetSymbolAddress((void**)&p_wihh, g_wihh);
    cudaGetSymbolAddress((void**)&p_wihl, g_wihl);

    cudaFuncSetAttribute(gemm_tc, cudaFuncAttributeMaxDynamicSharedMemorySize, GSM_TOTAL);
    cudaFuncSetAttribute(cell_tc, cudaFuncAttributeMaxDynamicSharedMemorySize, CSM_TOTAL);

    pack_whh<<<384, 256>>>(Whh_f, Whh_b);

    // operand plane pre-splits
    {
        int n4;
        n4 = NR * D_ / 4;
        split_k<<<(n4 + 255) / 256, 256>>>((const float4*)v,
            (__nv_bfloat162*)p_vh, (__nv_bfloat162*)p_vl, n4);
        n4 = 512 * 512 / 4;
        split_k<<<(n4 + 255) / 256, 256>>>((const float4*)W1,
            (__nv_bfloat162*)p_w12h, (__nv_bfloat162*)p_w12l, n4);
        split_k<<<(n4 + 255) / 256, 256>>>((const float4*)W2,
            (__nv_bfloat162*)(p_w12h + (size_t)512 * 512),
            (__nv_bfloat162*)(p_w12l + (size_t)512 * 512), n4);
        n4 = 1024 * 1024 / 4;
        split_k<<<(n4 + 255) / 256, 256>>>((const float4*)Wg,
            (__nv_bfloat162*)p_wgh, (__nv_bfloat162*)p_wgl, n4);
        n4 = 768 * 1024 / 4;
        split_k<<<(n4 + 255) / 256, 256>>>((const float4*)Wih_f,
            (__nv_bfloat162*)p_wihh, (__nv_bfloat162*)p_wihl, n4);
        split_k<<<(n4 + 255) / 256, 256>>>((const float4*)Wih_b,
            (__nv_bfloat162*)(p_wihh + (size_t)768 * 1024),
            (__nv_bfloat162*)(p_wihl + (size_t)768 * 1024), n4);
    }

    // [cwm | cm] = v @ [W1;W2]^T, split fp32 outputs
    gemm_tc<<<dim3(8, 160), 256, GSM_TOTAL>>>(
        p_vh, p_vl, nullptr, nullptr, p_w12h, p_w12l,
        b1, b2, nullptr, nullptr, p_cwm, p_cm, nullptr, nullptr, 1024, 512, 2);

    scores_k<<<dim3(5, 5, B_), 256>>>(v);
    softmax_k<<<2560, 256>>>();
    cell_tc<<<dim3(4, 5, B_), 256, CSM_TOTAL>>>();

    // gi planes = pg * sigmoid(pg @ Wg^T + bg), pg = [v | cell]
    gemm_tc<<<dim3(8, 160), 256, GSM_TOTAL>>>(
        p_vh, p_vl, p_ch, p_cl, p_wgh, p_wgl,
        bg, nullptr, v, p_cell, nullptr, nullptr, p_gph, p_gpl, 1024, 1024, 1);

    // merged gih = gi @ [Wih_f;Wih_b]^T  (bias folded into recur)
    gemm_tc<<<dim3(12, 160), 256, GSM_TOTAL>>>(
        p_gph, p_gpl, nullptr, nullptr, p_wihh, p_wihl,
        nullptr, nullptr, nullptr, nullptr, p_gih, nullptr, nullptr, nullptr, 1536, 1024, 0);

    recur_k<<<128, 256>>>(p_gih, bih_f, bhh_f, bih_b, bhh_b, out);
}